// round 4
// baseline (speedup 1.0000x reference)
#include <cuda_runtime.h>
#include <cuda_bf16.h>

#define NV  3
#define NN  4096
#define HH  256
#define CC  20
#define DYY 300
#define DD  512

// ---------------- scratch (static device globals; no runtime allocation) ----
__device__ float g_xp[(size_t)NV * NN * HH];   // leaky(x@W^T+b)
__device__ float g_xq[(size_t)NV * NN * HH];   // row-normalized xp
__device__ float g_xb[(size_t)NV * NN * HH];   // xp * mt[v,m]  (col-mask folded)
__device__ float g_s [(size_t)NN * NN];        // max_v exp(dot/beta)*masks, diag=0
__device__ float g_rowsum[NN];
__device__ float g_yn[CC * HH];                // sigmoid(y@Wy^T+by)

struct ProjPtrs {
    const float* x[NV];
    const float* W[NV];
    const float* b[NV];
    const int*   mask;   // (N, V) int32
};

// ---------------- K0: y_n = sigmoid(y @ Wy^T + by)  (C x H) -----------------
__global__ void k_yn(const float* __restrict__ y,
                     const float* __restrict__ Wy,
                     const float* __restrict__ by) {
    int c = blockIdx.x;
    int h = threadIdx.x;
    __shared__ float ys[DYY];
    for (int d = threadIdx.x; d < DYY; d += blockDim.x) ys[d] = y[c * DYY + d];
    __syncthreads();
    const float* wr = Wy + (size_t)h * DYY;
    float acc = 0.f;
#pragma unroll 4
    for (int d = 0; d < DYY; d++) acc = fmaf(ys[d], wr[d], acc);
    acc += by[h];
    g_yn[c * HH + h] = 1.f / (1.f + __expf(-acc));
}

// ---------------- K1: xp / xq / xb  --------------------------------------
// Tile: BM=64 rows x BN=256(=H) cols, BK=32. 256 threads: ty=tid/32 (8),
// tx=tid%32 (32). Thread tile 8x8. One warp owns complete rows -> norm via
// warp shuffle reduction.
__global__ __launch_bounds__(256, 1) void k_proj(ProjPtrs P) {
    int v  = blockIdx.y;
    int rb = blockIdx.x;                 // 64-row block
    int tid = threadIdx.x;
    int ty = tid >> 5;                   // 0..7
    int tx = tid & 31;                   // 0..31

    __shared__ float As[64 * 33];        // x tile   [row][k]
    __shared__ float Bs[32 * 260];       // W tile transposed [k][h]

    const float* xv = P.x[v];
    const float* Wv = P.W[v];

    float acc[8][8];
#pragma unroll
    for (int i = 0; i < 8; i++)
#pragma unroll
        for (int j = 0; j < 8; j++) acc[i][j] = 0.f;

    for (int k0 = 0; k0 < DD; k0 += 32) {
#pragma unroll
        for (int q = 0; q < 2; q++) {                   // A: 64x32 = 512 f4
            int l = tid * 2 + q;
            int r = l >> 3, kq = l & 7;
            float4 f = *(const float4*)(xv + (size_t)(rb * 64 + r) * DD + k0 + kq * 4);
            As[r * 33 + kq * 4 + 0] = f.x;
            As[r * 33 + kq * 4 + 1] = f.y;
            As[r * 33 + kq * 4 + 2] = f.z;
            As[r * 33 + kq * 4 + 3] = f.w;
        }
#pragma unroll
        for (int q = 0; q < 8; q++) {                   // B: 256x32 = 2048 f4
            int l = tid * 8 + q;
            int h = l >> 3, kq = l & 7;
            float4 f = *(const float4*)(Wv + (size_t)h * DD + k0 + kq * 4);
            Bs[(kq * 4 + 0) * 260 + h] = f.x;
            Bs[(kq * 4 + 1) * 260 + h] = f.y;
            Bs[(kq * 4 + 2) * 260 + h] = f.z;
            Bs[(kq * 4 + 3) * 260 + h] = f.w;
        }
        __syncthreads();
#pragma unroll
        for (int kk = 0; kk < 32; kk++) {
            float a[8];
#pragma unroll
            for (int i = 0; i < 8; i++) a[i] = As[(ty * 8 + i) * 33 + kk];
            float4 b0 = *(const float4*)&Bs[kk * 260 + tx * 8];
            float4 b1 = *(const float4*)&Bs[kk * 260 + tx * 8 + 4];
            float bb[8] = {b0.x, b0.y, b0.z, b0.w, b1.x, b1.y, b1.z, b1.w};
#pragma unroll
            for (int i = 0; i < 8; i++)
#pragma unroll
                for (int j = 0; j < 8; j++)
                    acc[i][j] = fmaf(a[i], bb[j], acc[i][j]);
        }
        __syncthreads();
    }

    // bias + leaky relu
    float bb[8];
#pragma unroll
    for (int j = 0; j < 8; j++) bb[j] = P.b[v][tx * 8 + j];
#pragma unroll
    for (int i = 0; i < 8; i++)
#pragma unroll
        for (int j = 0; j < 8; j++) {
            float t = acc[i][j] + bb[j];
            acc[i][j] = (t >= 0.f) ? t : 0.1f * t;
        }

    // per-row L2 norm (warp-wide: tx spans the full 256-col row)
#pragma unroll
    for (int i = 0; i < 8; i++) {
        float ss = 0.f;
#pragma unroll
        for (int j = 0; j < 8; j++) ss = fmaf(acc[i][j], acc[i][j], ss);
#pragma unroll
        for (int off = 16; off > 0; off >>= 1)
            ss += __shfl_xor_sync(0xFFFFFFFFu, ss, off);
        float rinv = 1.f / fmaxf(sqrtf(ss), 1e-12f);

        int n = rb * 64 + ty * 8 + i;
        float mrow = (float)P.mask[n * NV + v];
        size_t base = ((size_t)v * NN + n) * HH + tx * 8;

        float4 p0 = make_float4(acc[i][0], acc[i][1], acc[i][2], acc[i][3]);
        float4 p1 = make_float4(acc[i][4], acc[i][5], acc[i][6], acc[i][7]);
        *(float4*)(g_xp + base)     = p0;
        *(float4*)(g_xp + base + 4) = p1;
        float4 q0 = make_float4(p0.x * rinv, p0.y * rinv, p0.z * rinv, p0.w * rinv);
        float4 q1 = make_float4(p1.x * rinv, p1.y * rinv, p1.z * rinv, p1.w * rinv);
        *(float4*)(g_xq + base)     = q0;
        *(float4*)(g_xq + base + 4) = q1;
        float4 m0 = make_float4(p0.x * mrow, p0.y * mrow, p0.z * mrow, p0.w * mrow);
        float4 m1 = make_float4(p1.x * mrow, p1.y * mrow, p1.z * mrow, p1.w * mrow);
        *(float4*)(g_xb + base)     = m0;
        *(float4*)(g_xb + base + 4) = m1;
    }
}

// ---------------- K2: s = max_v exp(xq_v @ xq_v^T / beta)*masks, diag=0 ----
// Tile 128x128, BK=32, 256 threads (16x16), thread tile 8x8.
__global__ __launch_bounds__(256, 1) void k_smat(const int* __restrict__ mask) {
    int cb = blockIdx.x, rb = blockIdx.y;
    int tid = threadIdx.x;
    int ty = tid >> 4, tx = tid & 15;

    __shared__ float As[128 * 33];      // [row][k]
    __shared__ float Bs[32 * 132];      // [k][col] (transposed on load)

    float smax[8][8];
#pragma unroll
    for (int i = 0; i < 8; i++)
#pragma unroll
        for (int j = 0; j < 8; j++) smax[i][j] = 0.f;

    for (int v = 0; v < NV; v++) {
        const float* xq = g_xq + (size_t)v * NN * HH;
        float dot[8][8];
#pragma unroll
        for (int i = 0; i < 8; i++)
#pragma unroll
            for (int j = 0; j < 8; j++) dot[i][j] = 0.f;

        for (int k0 = 0; k0 < HH; k0 += 32) {
#pragma unroll
            for (int q = 0; q < 4; q++) {               // A: 128x32 = 1024 f4
                int l = tid * 4 + q;
                int r = l >> 3, kq = l & 7;
                float4 f = *(const float4*)(xq + (size_t)(rb * 128 + r) * HH + k0 + kq * 4);
                As[r * 33 + kq * 4 + 0] = f.x;
                As[r * 33 + kq * 4 + 1] = f.y;
                As[r * 33 + kq * 4 + 2] = f.z;
                As[r * 33 + kq * 4 + 3] = f.w;
            }
#pragma unroll
            for (int q = 0; q < 4; q++) {               // B: 128 cols x 32 k
                int l = tid * 4 + q;
                int col = l >> 3, kq = l & 7;
                float4 f = *(const float4*)(xq + (size_t)(cb * 128 + col) * HH + k0 + kq * 4);
                Bs[(kq * 4 + 0) * 132 + col] = f.x;
                Bs[(kq * 4 + 1) * 132 + col] = f.y;
                Bs[(kq * 4 + 2) * 132 + col] = f.z;
                Bs[(kq * 4 + 3) * 132 + col] = f.w;
            }
            __syncthreads();
#pragma unroll
            for (int kk = 0; kk < 32; kk++) {
                float a[8];
#pragma unroll
                for (int i = 0; i < 8; i++) a[i] = As[(ty * 8 + i) * 33 + kk];
                float4 b0 = *(const float4*)&Bs[kk * 132 + tx * 8];
                float4 b1 = *(const float4*)&Bs[kk * 132 + tx * 8 + 4];
                float bb[8] = {b0.x, b0.y, b0.z, b0.w, b1.x, b1.y, b1.z, b1.w};
#pragma unroll
                for (int i = 0; i < 8; i++)
#pragma unroll
                    for (int j = 0; j < 8; j++)
                        dot[i][j] = fmaf(a[i], bb[j], dot[i][j]);
            }
            __syncthreads();
        }

        int rm[8], cm[8];
#pragma unroll
        for (int i = 0; i < 8; i++) rm[i] = mask[(rb * 128 + ty * 8 + i) * NV + v];
#pragma unroll
        for (int j = 0; j < 8; j++) cm[j] = mask[(cb * 128 + tx * 8 + j) * NV + v];
#pragma unroll
        for (int i = 0; i < 8; i++)
#pragma unroll
            for (int j = 0; j < 8; j++)
                if (rm[i] && cm[j])
                    smax[i][j] = fmaxf(smax[i][j], __expf(dot[i][j] * 5.0f));
    }

    // zero diagonal, store
#pragma unroll
    for (int i = 0; i < 8; i++) {
        int n = rb * 128 + ty * 8 + i;
#pragma unroll
        for (int j = 0; j < 8; j++)
            if (n == cb * 128 + tx * 8 + j) smax[i][j] = 0.f;
        size_t base = (size_t)n * NN + cb * 128 + tx * 8;
        *(float4*)(g_s + base)     = make_float4(smax[i][0], smax[i][1], smax[i][2], smax[i][3]);
        *(float4*)(g_s + base + 4) = make_float4(smax[i][4], smax[i][5], smax[i][6], smax[i][7]);
    }
}

// ---------------- K3: rowsum + confi (row scan; fully deterministic) -------
__global__ void k_rowstats(const int* __restrict__ mask, float* __restrict__ confi_out) {
    int n = blockIdx.x;
    int tid = threadIdx.x;
    const float* srow = g_s + (size_t)n * NN;
    float sum = 0.f, c0 = 0.f, c1 = 0.f, c2 = 0.f;
    for (int m = tid; m < NN; m += 256) {
        float sv = srow[m];
        sum += sv;
        float lg = 0.2f * __logf(sv + 1e-9f);
        int m3 = m * NV;
        if (mask[m3 + 0]) c0 = fmaxf(c0, lg);
        if (mask[m3 + 1]) c1 = fmaxf(c1, lg);
        if (mask[m3 + 2]) c2 = fmaxf(c2, lg);
    }
    __shared__ float rs0[256], rs1[256], rs2[256], rs3[256];
    rs0[tid] = sum; rs1[tid] = c0; rs2[tid] = c1; rs3[tid] = c2;
    __syncthreads();
    for (int off = 128; off > 0; off >>= 1) {
        if (tid < off) {
            rs0[tid] += rs0[tid + off];
            rs1[tid] = fmaxf(rs1[tid], rs1[tid + off]);
            rs2[tid] = fmaxf(rs2[tid], rs2[tid + off]);
            rs3[tid] = fmaxf(rs3[tid], rs3[tid + off]);
        }
        __syncthreads();
    }
    if (tid == 0) {
        g_rowsum[n] = rs0[0];
        confi_out[0 * NN + n] = fminf(rs1[0], 1.0f);   // clip(.,0,1): values already >= 0
        confi_out[1 * NN + n] = fminf(rs2[0], 1.0f);
        confi_out[2 * NN + n] = fminf(rs3[0], 1.0f);
    }
}

// ---------------- K4: new_x = (s/rowsum) @ xb_v, blend, expand to Z --------
// Tile BM=64 rows x BN=128 h-cols, BK=32, 256 threads (16x16), tile 4x8.
// grid (N/64, H/128, V). Z written directly from the epilogue.
__global__ __launch_bounds__(256, 1) void k_newx_z(const int* __restrict__ mask,
                                                   float* __restrict__ out) {
    int rb = blockIdx.x, hb = blockIdx.y, v = blockIdx.z;
    int h0 = hb * 128;
    int tid = threadIdx.x;
    int ty = tid >> 4, tx = tid & 15;

    __shared__ float As[64 * 33];       // s tile   [row][m]
    __shared__ float Bs[32 * 132];      // xb tile  [m][h]
    __shared__ float yns[CC * 128];     // y_n slice for this h block

    for (int l = tid; l < CC * 128; l += 256) {
        int c = l >> 7, hh = l & 127;
        yns[l] = g_yn[c * HH + h0 + hh];
    }

    const float* xb = g_xb + (size_t)v * NN * HH;
    float acc[4][8];
#pragma unroll
    for (int i = 0; i < 4; i++)
#pragma unroll
        for (int j = 0; j < 8; j++) acc[i][j] = 0.f;

    for (int m0 = 0; m0 < NN; m0 += 32) {
#pragma unroll
        for (int q = 0; q < 2; q++) {                   // A: 64x32 = 512 f4
            int l = tid * 2 + q;
            int r = l >> 3, kq = l & 7;
            float4 f = *(const float4*)(g_s + (size_t)(rb * 64 + r) * NN + m0 + kq * 4);
            As[r * 33 + kq * 4 + 0] = f.x;
            As[r * 33 + kq * 4 + 1] = f.y;
            As[r * 33 + kq * 4 + 2] = f.z;
            As[r * 33 + kq * 4 + 3] = f.w;
        }
#pragma unroll
        for (int q = 0; q < 4; q++) {                   // B: 32x128 = 1024 f4 (no transpose)
            int l = tid * 4 + q;
            int kr = l >> 5, c4 = l & 31;
            float4 f = *(const float4*)(xb + (size_t)(m0 + kr) * HH + h0 + c4 * 4);
            *(float4*)&Bs[kr * 132 + c4 * 4] = f;
        }
        __syncthreads();
#pragma unroll
        for (int kk = 0; kk < 32; kk++) {
            float a[4];
#pragma unroll
            for (int i = 0; i < 4; i++) a[i] = As[(ty * 4 + i) * 33 + kk];
            float4 b0 = *(const float4*)&Bs[kk * 132 + tx * 8];
            float4 b1 = *(const float4*)&Bs[kk * 132 + tx * 8 + 4];
            float bb[8] = {b0.x, b0.y, b0.z, b0.w, b1.x, b1.y, b1.z, b1.w};
#pragma unroll
            for (int i = 0; i < 4; i++)
#pragma unroll
                for (int j = 0; j < 8; j++)
                    acc[i][j] = fmaf(a[i], bb[j], acc[i][j]);
        }
        __syncthreads();
    }

    // epilogue: scale by 1/(rowsum+1e-9), blend with xp by row-mask, expand by y_n
#pragma unroll
    for (int i = 0; i < 4; i++) {
        int n = rb * 64 + ty * 4 + i;
        float rinv = 1.f / (g_rowsum[n] + 1e-9f);
        int mrow = mask[n * NV + v];
        float nx[8];
        if (mrow) {
            const float* xpr = g_xp + ((size_t)v * NN + n) * HH + h0 + tx * 8;
            float4 p0 = *(const float4*)xpr;
            float4 p1 = *(const float4*)(xpr + 4);
            nx[0] = p0.x; nx[1] = p0.y; nx[2] = p0.z; nx[3] = p0.w;
            nx[4] = p1.x; nx[5] = p1.y; nx[6] = p1.z; nx[7] = p1.w;
        } else {
#pragma unroll
            for (int j = 0; j < 8; j++) nx[j] = acc[i][j] * rinv;
        }
        size_t zrow = ((size_t)v * NN + n) * CC * HH + h0 + tx * 8;
#pragma unroll
        for (int c = 0; c < CC; c++) {
            float4 y0 = *(const float4*)&yns[c * 128 + tx * 8];
            float4 y1 = *(const float4*)&yns[c * 128 + tx * 8 + 4];
            float4 o0 = make_float4(nx[0] * y0.x, nx[1] * y0.y, nx[2] * y0.z, nx[3] * y0.w);
            float4 o1 = make_float4(nx[4] * y1.x, nx[5] * y1.y, nx[6] * y1.z, nx[7] * y1.w);
            *(float4*)(out + zrow + (size_t)c * HH)     = o0;
            *(float4*)(out + zrow + (size_t)c * HH + 4) = o1;
        }
    }
}

// ---------------- launch ----------------------------------------------------
extern "C" void kernel_launch(void* const* d_in, const int* in_sizes, int n_in,
                              void* d_out, int out_size) {
    ProjPtrs P{};
    const float* yv  = nullptr;
    const float* Wy  = nullptr;
    const float* byp = nullptr;
    const int*   mask = nullptr;
    int nx = 0, nW = 0, nb = 0;
    for (int i = 0; i < n_in; i++) {
        int s = in_sizes[i];
        if      (s == NN * DD)  { if (nx < NV) P.x[nx++] = (const float*)d_in[i]; }
        else if (s == HH * DD)  { if (nW < NV) P.W[nW++] = (const float*)d_in[i]; }
        else if (s == CC * DYY) yv = (const float*)d_in[i];
        else if (s == HH * DYY) Wy = (const float*)d_in[i];
        else if (s == NN * NV)  mask = (const int*)d_in[i];
        else if (s == HH) {
            if (nb < NV) P.b[nb++] = (const float*)d_in[i];
            else         byp = (const float*)d_in[i];
        }
    }
    P.mask = mask;
    float* out = (float*)d_out;
    float* confi_out = out + ((size_t)out_size - (size_t)NV * NN);

    k_yn      <<<CC, HH>>>(yv, Wy, byp);
    k_proj    <<<dim3(NN / 64, NV), 256>>>(P);
    k_smat    <<<dim3(NN / 128, NN / 128), 256>>>(mask);
    k_rowstats<<<NN, 256>>>(mask, confi_out);
    k_newx_z  <<<dim3(NN / 64, HH / 128, NV), 256>>>(mask, out);
}

// round 6
// speedup vs baseline: 1.0007x; 1.0007x over previous
#include <cuda_runtime.h>
#include <cuda_bf16.h>

#define NV  3
#define NN  4096
#define HH  256
#define CC  20
#define DYY 300
#define DD  512

// ---------------- scratch (static device globals; no runtime allocation) ----
__device__ float g_xp[(size_t)NV * NN * HH];   // leaky(x@W^T+b)
__device__ float g_xq[(size_t)NV * NN * HH];   // row-normalized xp
__device__ float g_xb[(size_t)NV * NN * HH];   // xp * mt[v,m]  (col-mask folded)
__device__ float g_s [(size_t)NN * NN];        // max_v exp(dot/beta)*masks, diag=0
__device__ float g_rowsum[NN];
__device__ float g_yn[CC * HH];                // sigmoid(y@Wy^T+by)

struct ProjPtrs {
    const float* x[NV];
    const float* W[NV];
    const float* b[NV];
    const int*   mask;   // (N, V) int32
};

// ---------------- K0: y_n = sigmoid(y @ Wy^T + by)  (C x H) -----------------
__global__ void k_yn(const float* __restrict__ y,
                     const float* __restrict__ Wy,
                     const float* __restrict__ by) {
    int c = blockIdx.x;
    int h = threadIdx.x;
    __shared__ float ys[DYY];
    for (int d = threadIdx.x; d < DYY; d += blockDim.x) ys[d] = y[c * DYY + d];
    __syncthreads();
    const float* wr = Wy + (size_t)h * DYY;
    float acc = 0.f;
#pragma unroll 4
    for (int d = 0; d < DYY; d++) acc = fmaf(ys[d], wr[d], acc);
    acc += by[h];
    g_yn[c * HH + h] = 1.f / (1.f + __expf(-acc));
}

// ---------------- K1: xp / xq / xb  --------------------------------------
// Tile: BM=64 rows x BN=256(=H) cols, BK=32. 256 threads: ty=tid/32 (8),
// tx=tid%32 (32). Thread tile 8x8. One warp owns complete rows -> norm via
// warp shuffle reduction.
__global__ __launch_bounds__(256, 1) void k_proj(ProjPtrs P) {
    int v  = blockIdx.y;
    int rb = blockIdx.x;                 // 64-row block
    int tid = threadIdx.x;
    int ty = tid >> 5;                   // 0..7
    int tx = tid & 31;                   // 0..31

    __shared__ float As[64 * 33];        // x tile   [row][k]
    __shared__ float Bs[32 * 260];       // W tile transposed [k][h]

    const float* xv = P.x[v];
    const float* Wv = P.W[v];

    float acc[8][8];
#pragma unroll
    for (int i = 0; i < 8; i++)
#pragma unroll
        for (int j = 0; j < 8; j++) acc[i][j] = 0.f;

    for (int k0 = 0; k0 < DD; k0 += 32) {
#pragma unroll
        for (int q = 0; q < 2; q++) {                   // A: 64x32 = 512 f4
            int l = tid * 2 + q;
            int r = l >> 3, kq = l & 7;
            float4 f = *(const float4*)(xv + (size_t)(rb * 64 + r) * DD + k0 + kq * 4);
            As[r * 33 + kq * 4 + 0] = f.x;
            As[r * 33 + kq * 4 + 1] = f.y;
            As[r * 33 + kq * 4 + 2] = f.z;
            As[r * 33 + kq * 4 + 3] = f.w;
        }
#pragma unroll
        for (int q = 0; q < 8; q++) {                   // B: 256x32 = 2048 f4
            int l = tid * 8 + q;
            int h = l >> 3, kq = l & 7;
            float4 f = *(const float4*)(Wv + (size_t)h * DD + k0 + kq * 4);
            Bs[(kq * 4 + 0) * 260 + h] = f.x;
            Bs[(kq * 4 + 1) * 260 + h] = f.y;
            Bs[(kq * 4 + 2) * 260 + h] = f.z;
            Bs[(kq * 4 + 3) * 260 + h] = f.w;
        }
        __syncthreads();
#pragma unroll
        for (int kk = 0; kk < 32; kk++) {
            float a[8];
#pragma unroll
            for (int i = 0; i < 8; i++) a[i] = As[(ty * 8 + i) * 33 + kk];
            float4 b0 = *(const float4*)&Bs[kk * 260 + tx * 8];
            float4 b1 = *(const float4*)&Bs[kk * 260 + tx * 8 + 4];
            float bb[8] = {b0.x, b0.y, b0.z, b0.w, b1.x, b1.y, b1.z, b1.w};
#pragma unroll
            for (int i = 0; i < 8; i++)
#pragma unroll
                for (int j = 0; j < 8; j++)
                    acc[i][j] = fmaf(a[i], bb[j], acc[i][j]);
        }
        __syncthreads();
    }

    // bias + leaky relu
    float bb[8];
#pragma unroll
    for (int j = 0; j < 8; j++) bb[j] = P.b[v][tx * 8 + j];
#pragma unroll
    for (int i = 0; i < 8; i++)
#pragma unroll
        for (int j = 0; j < 8; j++) {
            float t = acc[i][j] + bb[j];
            acc[i][j] = (t >= 0.f) ? t : 0.1f * t;
        }

    // per-row L2 norm (warp-wide: tx spans the full 256-col row)
#pragma unroll
    for (int i = 0; i < 8; i++) {
        float ss = 0.f;
#pragma unroll
        for (int j = 0; j < 8; j++) ss = fmaf(acc[i][j], acc[i][j], ss);
#pragma unroll
        for (int off = 16; off > 0; off >>= 1)
            ss += __shfl_xor_sync(0xFFFFFFFFu, ss, off);
        float rinv = 1.f / fmaxf(sqrtf(ss), 1e-12f);

        int n = rb * 64 + ty * 8 + i;
        float mrow = (float)P.mask[n * NV + v];
        size_t base = ((size_t)v * NN + n) * HH + tx * 8;

        float4 p0 = make_float4(acc[i][0], acc[i][1], acc[i][2], acc[i][3]);
        float4 p1 = make_float4(acc[i][4], acc[i][5], acc[i][6], acc[i][7]);
        *(float4*)(g_xp + base)     = p0;
        *(float4*)(g_xp + base + 4) = p1;
        float4 q0 = make_float4(p0.x * rinv, p0.y * rinv, p0.z * rinv, p0.w * rinv);
        float4 q1 = make_float4(p1.x * rinv, p1.y * rinv, p1.z * rinv, p1.w * rinv);
        *(float4*)(g_xq + base)     = q0;
        *(float4*)(g_xq + base + 4) = q1;
        float4 m0 = make_float4(p0.x * mrow, p0.y * mrow, p0.z * mrow, p0.w * mrow);
        float4 m1 = make_float4(p1.x * mrow, p1.y * mrow, p1.z * mrow, p1.w * mrow);
        *(float4*)(g_xb + base)     = m0;
        *(float4*)(g_xb + base + 4) = m1;
    }
}

// ---------------- K2: s = max_v exp(xq_v @ xq_v^T / beta)*masks, diag=0 ----
// Tile 128x128, BK=32, 256 threads (16x16), thread tile 8x8.
__global__ __launch_bounds__(256, 1) void k_smat(const int* __restrict__ mask) {
    int cb = blockIdx.x, rb = blockIdx.y;
    int tid = threadIdx.x;
    int ty = tid >> 4, tx = tid & 15;

    __shared__ float As[128 * 33];      // [row][k]
    __shared__ float Bs[32 * 132];      // [k][col] (transposed on load)

    float smax[8][8];
#pragma unroll
    for (int i = 0; i < 8; i++)
#pragma unroll
        for (int j = 0; j < 8; j++) smax[i][j] = 0.f;

    for (int v = 0; v < NV; v++) {
        const float* xq = g_xq + (size_t)v * NN * HH;
        float dot[8][8];
#pragma unroll
        for (int i = 0; i < 8; i++)
#pragma unroll
            for (int j = 0; j < 8; j++) dot[i][j] = 0.f;

        for (int k0 = 0; k0 < HH; k0 += 32) {
#pragma unroll
            for (int q = 0; q < 4; q++) {               // A: 128x32 = 1024 f4
                int l = tid * 4 + q;
                int r = l >> 3, kq = l & 7;
                float4 f = *(const float4*)(xq + (size_t)(rb * 128 + r) * HH + k0 + kq * 4);
                As[r * 33 + kq * 4 + 0] = f.x;
                As[r * 33 + kq * 4 + 1] = f.y;
                As[r * 33 + kq * 4 + 2] = f.z;
                As[r * 33 + kq * 4 + 3] = f.w;
            }
#pragma unroll
            for (int q = 0; q < 4; q++) {               // B: 128 cols x 32 k
                int l = tid * 4 + q;
                int col = l >> 3, kq = l & 7;
                float4 f = *(const float4*)(xq + (size_t)(cb * 128 + col) * HH + k0 + kq * 4);
                Bs[(kq * 4 + 0) * 132 + col] = f.x;
                Bs[(kq * 4 + 1) * 132 + col] = f.y;
                Bs[(kq * 4 + 2) * 132 + col] = f.z;
                Bs[(kq * 4 + 3) * 132 + col] = f.w;
            }
            __syncthreads();
#pragma unroll
            for (int kk = 0; kk < 32; kk++) {
                float a[8];
#pragma unroll
                for (int i = 0; i < 8; i++) a[i] = As[(ty * 8 + i) * 33 + kk];
                float4 b0 = *(const float4*)&Bs[kk * 132 + tx * 8];
                float4 b1 = *(const float4*)&Bs[kk * 132 + tx * 8 + 4];
                float bb[8] = {b0.x, b0.y, b0.z, b0.w, b1.x, b1.y, b1.z, b1.w};
#pragma unroll
                for (int i = 0; i < 8; i++)
#pragma unroll
                    for (int j = 0; j < 8; j++)
                        dot[i][j] = fmaf(a[i], bb[j], dot[i][j]);
            }
            __syncthreads();
        }

        int rm[8], cm[8];
#pragma unroll
        for (int i = 0; i < 8; i++) rm[i] = mask[(rb * 128 + ty * 8 + i) * NV + v];
#pragma unroll
        for (int j = 0; j < 8; j++) cm[j] = mask[(cb * 128 + tx * 8 + j) * NV + v];
#pragma unroll
        for (int i = 0; i < 8; i++)
#pragma unroll
            for (int j = 0; j < 8; j++)
                if (rm[i] && cm[j])
                    smax[i][j] = fmaxf(smax[i][j], __expf(dot[i][j] * 5.0f));
    }

    // zero diagonal, store
#pragma unroll
    for (int i = 0; i < 8; i++) {
        int n = rb * 128 + ty * 8 + i;
#pragma unroll
        for (int j = 0; j < 8; j++)
            if (n == cb * 128 + tx * 8 + j) smax[i][j] = 0.f;
        size_t base = (size_t)n * NN + cb * 128 + tx * 8;
        *(float4*)(g_s + base)     = make_float4(smax[i][0], smax[i][1], smax[i][2], smax[i][3]);
        *(float4*)(g_s + base + 4) = make_float4(smax[i][4], smax[i][5], smax[i][6], smax[i][7]);
    }
}

// ---------------- K3: rowsum + confi (row scan; fully deterministic) -------
__global__ void k_rowstats(const int* __restrict__ mask, float* __restrict__ confi_out) {
    int n = blockIdx.x;
    int tid = threadIdx.x;
    const float* srow = g_s + (size_t)n * NN;
    float sum = 0.f, c0 = 0.f, c1 = 0.f, c2 = 0.f;
    for (int m = tid; m < NN; m += 256) {
        float sv = srow[m];
        sum += sv;
        float lg = 0.2f * __logf(sv + 1e-9f);
        int m3 = m * NV;
        if (mask[m3 + 0]) c0 = fmaxf(c0, lg);
        if (mask[m3 + 1]) c1 = fmaxf(c1, lg);
        if (mask[m3 + 2]) c2 = fmaxf(c2, lg);
    }
    __shared__ float rs0[256], rs1[256], rs2[256], rs3[256];
    rs0[tid] = sum; rs1[tid] = c0; rs2[tid] = c1; rs3[tid] = c2;
    __syncthreads();
    for (int off = 128; off > 0; off >>= 1) {
        if (tid < off) {
            rs0[tid] += rs0[tid + off];
            rs1[tid] = fmaxf(rs1[tid], rs1[tid + off]);
            rs2[tid] = fmaxf(rs2[tid], rs2[tid + off]);
            rs3[tid] = fmaxf(rs3[tid], rs3[tid + off]);
        }
        __syncthreads();
    }
    if (tid == 0) {
        g_rowsum[n] = rs0[0];
        confi_out[0 * NN + n] = fminf(rs1[0], 1.0f);   // clip(.,0,1): values already >= 0
        confi_out[1 * NN + n] = fminf(rs2[0], 1.0f);
        confi_out[2 * NN + n] = fminf(rs3[0], 1.0f);
    }
}

// ---------------- K4: new_x = (s/rowsum) @ xb_v, blend, expand to Z --------
// Tile BM=64 rows x BN=128 h-cols, BK=32, 256 threads (16x16), tile 4x8.
// grid (N/64, H/128, V). Z written directly from the epilogue.
__global__ __launch_bounds__(256, 1) void k_newx_z(const int* __restrict__ mask,
                                                   float* __restrict__ out) {
    int rb = blockIdx.x, hb = blockIdx.y, v = blockIdx.z;
    int h0 = hb * 128;
    int tid = threadIdx.x;
    int ty = tid >> 4, tx = tid & 15;

    __shared__ float As[64 * 33];       // s tile   [row][m]
    __shared__ float Bs[32 * 132];      // xb tile  [m][h]
    __shared__ float yns[CC * 128];     // y_n slice for this h block

    for (int l = tid; l < CC * 128; l += 256) {
        int c = l >> 7, hh = l & 127;
        yns[l] = g_yn[c * HH + h0 + hh];
    }

    const float* xb = g_xb + (size_t)v * NN * HH;
    float acc[4][8];
#pragma unroll
    for (int i = 0; i < 4; i++)
#pragma unroll
        for (int j = 0; j < 8; j++) acc[i][j] = 0.f;

    for (int m0 = 0; m0 < NN; m0 += 32) {
#pragma unroll
        for (int q = 0; q < 2; q++) {                   // A: 64x32 = 512 f4
            int l = tid * 2 + q;
            int r = l >> 3, kq = l & 7;
            float4 f = *(const float4*)(g_s + (size_t)(rb * 64 + r) * NN + m0 + kq * 4);
            As[r * 33 + kq * 4 + 0] = f.x;
            As[r * 33 + kq * 4 + 1] = f.y;
            As[r * 33 + kq * 4 + 2] = f.z;
            As[r * 33 + kq * 4 + 3] = f.w;
        }
#pragma unroll
        for (int q = 0; q < 4; q++) {                   // B: 32x128 = 1024 f4 (no transpose)
            int l = tid * 4 + q;
            int kr = l >> 5, c4 = l & 31;
            float4 f = *(const float4*)(xb + (size_t)(m0 + kr) * HH + h0 + c4 * 4);
            *(float4*)&Bs[kr * 132 + c4 * 4] = f;
        }
        __syncthreads();
#pragma unroll
        for (int kk = 0; kk < 32; kk++) {
            float a[4];
#pragma unroll
            for (int i = 0; i < 4; i++) a[i] = As[(ty * 4 + i) * 33 + kk];
            float4 b0 = *(const float4*)&Bs[kk * 132 + tx * 8];
            float4 b1 = *(const float4*)&Bs[kk * 132 + tx * 8 + 4];
            float bb[8] = {b0.x, b0.y, b0.z, b0.w, b1.x, b1.y, b1.z, b1.w};
#pragma unroll
            for (int i = 0; i < 4; i++)
#pragma unroll
                for (int j = 0; j < 8; j++)
                    acc[i][j] = fmaf(a[i], bb[j], acc[i][j]);
        }
        __syncthreads();
    }

    // epilogue: scale by 1/(rowsum+1e-9), blend with xp by row-mask, expand by y_n
#pragma unroll
    for (int i = 0; i < 4; i++) {
        int n = rb * 64 + ty * 4 + i;
        float rinv = 1.f / (g_rowsum[n] + 1e-9f);
        int mrow = mask[n * NV + v];
        float nx[8];
        if (mrow) {
            const float* xpr = g_xp + ((size_t)v * NN + n) * HH + h0 + tx * 8;
            float4 p0 = *(const float4*)xpr;
            float4 p1 = *(const float4*)(xpr + 4);
            nx[0] = p0.x; nx[1] = p0.y; nx[2] = p0.z; nx[3] = p0.w;
            nx[4] = p1.x; nx[5] = p1.y; nx[6] = p1.z; nx[7] = p1.w;
        } else {
#pragma unroll
            for (int j = 0; j < 8; j++) nx[j] = acc[i][j] * rinv;
        }
        size_t zrow = ((size_t)v * NN + n) * CC * HH + h0 + tx * 8;
#pragma unroll
        for (int c = 0; c < CC; c++) {
            float4 y0 = *(const float4*)&yns[c * 128 + tx * 8];
            float4 y1 = *(const float4*)&yns[c * 128 + tx * 8 + 4];
            float4 o0 = make_float4(nx[0] * y0.x, nx[1] * y0.y, nx[2] * y0.z, nx[3] * y0.w);
            float4 o1 = make_float4(nx[4] * y1.x, nx[5] * y1.y, nx[6] * y1.z, nx[7] * y1.w);
            *(float4*)(out + zrow + (size_t)c * HH)     = o0;
            *(float4*)(out + zrow + (size_t)c * HH + 4) = o1;
        }
    }
}

// ---------------- launch ----------------------------------------------------
extern "C" void kernel_launch(void* const* d_in, const int* in_sizes, int n_in,
                              void* d_out, int out_size) {
    ProjPtrs P{};
    const float* yv  = nullptr;
    const float* Wy  = nullptr;
    const float* byp = nullptr;
    const int*   mask = nullptr;
    int nx = 0, nW = 0, nb = 0;
    for (int i = 0; i < n_in; i++) {
        int s = in_sizes[i];
        if      (s == NN * DD)  { if (nx < NV) P.x[nx++] = (const float*)d_in[i]; }
        else if (s == HH * DD)  { if (nW < NV) P.W[nW++] = (const float*)d_in[i]; }
        else if (s == CC * DYY) yv = (const float*)d_in[i];
        else if (s == HH * DYY) Wy = (const float*)d_in[i];
        else if (s == NN * NV)  mask = (const int*)d_in[i];
        else if (s == HH) {
            if (nb < NV) P.b[nb++] = (const float*)d_in[i];
            else         byp = (const float*)d_in[i];
        }
    }
    P.mask = mask;
    float* out = (float*)d_out;
    float* confi_out = out + ((size_t)out_size - (size_t)NV * NN);

    k_yn      <<<CC, HH>>>(yv, Wy, byp);
    k_proj    <<<dim3(NN / 64, NV), 256>>>(P);
    k_smat    <<<dim3(NN / 128, NN / 128), 256>>>(mask);
    k_rowstats<<<NN, 256>>>(mask, confi_out);
    k_newx_z  <<<dim3(NN / 64, HH / 128, NV), 256>>>(mask, out);
}

// round 7
// speedup vs baseline: 2.1737x; 2.1722x over previous
#include <cuda_runtime.h>
#include <cuda_bf16.h>

#define NV  3
#define NN  4096
#define HH  256
#define CC  20
#define DYY 300
#define DD  512

// ---------------- scratch (static device globals; no runtime allocation) ----
__device__ float g_xp[(size_t)NV * NN * HH];   // leaky(x@W^T+b)
__device__ float g_xq[(size_t)NV * NN * HH];   // row-normalized xp
__device__ float g_xb[(size_t)NV * NN * HH];   // xp * mt[v,m]  (col-mask folded)
__device__ float g_s [(size_t)NN * NN];        // max_v exp(dot/beta)*masks, diag=0
__device__ float g_rowsum[NN];
__device__ float g_yn[CC * HH];                // sigmoid(y@Wy^T+by)

struct ProjPtrs {
    const float* x[NV];
    const float* W[NV];
    const float* b[NV];
    const int*   mask;   // (N, V) int32
};

// ---------------- tf32 helpers ---------------------------------------------
__device__ __forceinline__ unsigned f2tf(float f) {
    unsigned u;
    asm("cvt.rna.tf32.f32 %0, %1;" : "=r"(u) : "f"(f));
    return u;
}
__device__ __forceinline__ void mma_tf32(float* d, const unsigned* a, const unsigned* b) {
    asm volatile(
        "mma.sync.aligned.m16n8k8.row.col.f32.tf32.tf32.f32 "
        "{%0,%1,%2,%3},{%4,%5,%6,%7},{%8,%9},{%0,%1,%2,%3};"
        : "+f"(d[0]), "+f"(d[1]), "+f"(d[2]), "+f"(d[3])
        : "r"(a[0]), "r"(a[1]), "r"(a[2]), "r"(a[3]), "r"(b[0]), "r"(b[1]));
}

// ---------------- K0: y_n = sigmoid(y @ Wy^T + by)  (C x H) -----------------
__global__ void k_yn(const float* __restrict__ y,
                     const float* __restrict__ Wy,
                     const float* __restrict__ by) {
    int c = blockIdx.x;
    int h = threadIdx.x;
    __shared__ float ys[DYY];
    for (int d = threadIdx.x; d < DYY; d += blockDim.x) ys[d] = y[c * DYY + d];
    __syncthreads();
    const float* wr = Wy + (size_t)h * DYY;
    float acc = 0.f;
#pragma unroll 4
    for (int d = 0; d < DYY; d++) acc = fmaf(ys[d], wr[d], acc);
    acc += by[h];
    g_yn[c * HH + h] = 1.f / (1.f + __expf(-acc));
}

// ---------------- K1: xp / xq / xb (FFMA; 3.2 GFLOP, not the bottleneck) ---
__global__ __launch_bounds__(256, 1) void k_proj(ProjPtrs P) {
    int v  = blockIdx.y;
    int rb = blockIdx.x;
    int tid = threadIdx.x;
    int ty = tid >> 5;
    int tx = tid & 31;

    __shared__ float As[64 * 33];
    __shared__ float Bs[32 * 260];

    const float* xv = P.x[v];
    const float* Wv = P.W[v];

    float acc[8][8];
#pragma unroll
    for (int i = 0; i < 8; i++)
#pragma unroll
        for (int j = 0; j < 8; j++) acc[i][j] = 0.f;

    for (int k0 = 0; k0 < DD; k0 += 32) {
#pragma unroll
        for (int q = 0; q < 2; q++) {
            int l = tid * 2 + q;
            int r = l >> 3, kq = l & 7;
            float4 f = *(const float4*)(xv + (size_t)(rb * 64 + r) * DD + k0 + kq * 4);
            As[r * 33 + kq * 4 + 0] = f.x;
            As[r * 33 + kq * 4 + 1] = f.y;
            As[r * 33 + kq * 4 + 2] = f.z;
            As[r * 33 + kq * 4 + 3] = f.w;
        }
#pragma unroll
        for (int q = 0; q < 8; q++) {
            int l = tid * 8 + q;
            int h = l >> 3, kq = l & 7;
            float4 f = *(const float4*)(Wv + (size_t)h * DD + k0 + kq * 4);
            Bs[(kq * 4 + 0) * 260 + h] = f.x;
            Bs[(kq * 4 + 1) * 260 + h] = f.y;
            Bs[(kq * 4 + 2) * 260 + h] = f.z;
            Bs[(kq * 4 + 3) * 260 + h] = f.w;
        }
        __syncthreads();
#pragma unroll
        for (int kk = 0; kk < 32; kk++) {
            float a[8];
#pragma unroll
            for (int i = 0; i < 8; i++) a[i] = As[(ty * 8 + i) * 33 + kk];
            float4 b0 = *(const float4*)&Bs[kk * 260 + tx * 8];
            float4 b1 = *(const float4*)&Bs[kk * 260 + tx * 8 + 4];
            float bb[8] = {b0.x, b0.y, b0.z, b0.w, b1.x, b1.y, b1.z, b1.w};
#pragma unroll
            for (int i = 0; i < 8; i++)
#pragma unroll
                for (int j = 0; j < 8; j++)
                    acc[i][j] = fmaf(a[i], bb[j], acc[i][j]);
        }
        __syncthreads();
    }

    float bb[8];
#pragma unroll
    for (int j = 0; j < 8; j++) bb[j] = P.b[v][tx * 8 + j];
#pragma unroll
    for (int i = 0; i < 8; i++)
#pragma unroll
        for (int j = 0; j < 8; j++) {
            float t = acc[i][j] + bb[j];
            acc[i][j] = (t >= 0.f) ? t : 0.1f * t;
        }

#pragma unroll
    for (int i = 0; i < 8; i++) {
        float ss = 0.f;
#pragma unroll
        for (int j = 0; j < 8; j++) ss = fmaf(acc[i][j], acc[i][j], ss);
#pragma unroll
        for (int off = 16; off > 0; off >>= 1)
            ss += __shfl_xor_sync(0xFFFFFFFFu, ss, off);
        float rinv = 1.f / fmaxf(sqrtf(ss), 1e-12f);

        int n = rb * 64 + ty * 8 + i;
        float mrow = (float)P.mask[n * NV + v];
        size_t base = ((size_t)v * NN + n) * HH + tx * 8;

        float4 p0 = make_float4(acc[i][0], acc[i][1], acc[i][2], acc[i][3]);
        float4 p1 = make_float4(acc[i][4], acc[i][5], acc[i][6], acc[i][7]);
        *(float4*)(g_xp + base)     = p0;
        *(float4*)(g_xp + base + 4) = p1;
        float4 q0 = make_float4(p0.x * rinv, p0.y * rinv, p0.z * rinv, p0.w * rinv);
        float4 q1 = make_float4(p1.x * rinv, p1.y * rinv, p1.z * rinv, p1.w * rinv);
        *(float4*)(g_xq + base)     = q0;
        *(float4*)(g_xq + base + 4) = q1;
        float4 m0 = make_float4(p0.x * mrow, p0.y * mrow, p0.z * mrow, p0.w * mrow);
        float4 m1 = make_float4(p1.x * mrow, p1.y * mrow, p1.z * mrow, p1.w * mrow);
        *(float4*)(g_xb + base)     = m0;
        *(float4*)(g_xb + base + 4) = m1;
    }
}

// ---------------- K2: s = max_v exp(xq_v @ xq_v^T / beta)*masks, diag=0 ----
// tf32 mma.sync. Block tile 128x128, 8 warps (2x4), warp tile 64x32
// (4 m-tiles x 4 n-tiles of m16n8k8). Smem pad 36 -> conflict-free frags.
__global__ __launch_bounds__(256, 1) void k_smat_tc(const int* __restrict__ mask) {
    int cb = blockIdx.x, rb = blockIdx.y;
    int tid = threadIdx.x, lane = tid & 31, wid = tid >> 5;
    int wm = wid >> 2, wn = wid & 3;
    int g = lane >> 2, tg = lane & 3;

    __shared__ unsigned As[128 * 36];
    __shared__ unsigned Bs[128 * 36];
    __shared__ int rm_s[NV][128], cm_s[NV][128];

    for (int l = tid; l < 128; l += 256) {
#pragma unroll
        for (int v = 0; v < NV; v++) {
            rm_s[v][l] = mask[(rb * 128 + l) * NV + v];
            cm_s[v][l] = mask[(cb * 128 + l) * NV + v];
        }
    }

    float smax[16][4];
#pragma unroll
    for (int t = 0; t < 16; t++)
#pragma unroll
        for (int e = 0; e < 4; e++) smax[t][e] = 0.f;

    for (int v = 0; v < NV; v++) {
        const float* xq = g_xq + (size_t)v * NN * HH;
        float dot[16][4];
#pragma unroll
        for (int t = 0; t < 16; t++)
#pragma unroll
            for (int e = 0; e < 4; e++) dot[t][e] = 0.f;

        for (int k0 = 0; k0 < HH; k0 += 32) {
#pragma unroll
            for (int q = 0; q < 4; q++) {                // 128 rows x 32 k each side
                int l = q * 256 + tid;
                int r = l >> 3, kq = l & 7;
                float4 fa = *(const float4*)(xq + (size_t)(rb * 128 + r) * HH + k0 + kq * 4);
                As[r * 36 + kq * 4 + 0] = f2tf(fa.x);
                As[r * 36 + kq * 4 + 1] = f2tf(fa.y);
                As[r * 36 + kq * 4 + 2] = f2tf(fa.z);
                As[r * 36 + kq * 4 + 3] = f2tf(fa.w);
                float4 fb = *(const float4*)(xq + (size_t)(cb * 128 + r) * HH + k0 + kq * 4);
                Bs[r * 36 + kq * 4 + 0] = f2tf(fb.x);
                Bs[r * 36 + kq * 4 + 1] = f2tf(fb.y);
                Bs[r * 36 + kq * 4 + 2] = f2tf(fb.z);
                Bs[r * 36 + kq * 4 + 3] = f2tf(fb.w);
            }
            __syncthreads();
#pragma unroll
            for (int ks = 0; ks < 4; ks++) {
                int ca = ks * 8 + tg;
                unsigned a[4][4], b[4][2];
#pragma unroll
                for (int i = 0; i < 4; i++) {
                    int r = wm * 64 + i * 16 + g;
                    a[i][0] = As[r * 36 + ca];
                    a[i][1] = As[(r + 8) * 36 + ca];
                    a[i][2] = As[r * 36 + ca + 4];
                    a[i][3] = As[(r + 8) * 36 + ca + 4];
                }
#pragma unroll
                for (int j = 0; j < 4; j++) {
                    int c = wn * 32 + j * 8 + g;
                    b[j][0] = Bs[c * 36 + ca];
                    b[j][1] = Bs[c * 36 + ca + 4];
                }
#pragma unroll
                for (int i = 0; i < 4; i++)
#pragma unroll
                    for (int j = 0; j < 4; j++)
                        mma_tf32(dot[i * 4 + j], a[i], b[j]);
            }
            __syncthreads();
        }

        // merge: exp, mask, running max over v
#pragma unroll
        for (int i = 0; i < 4; i++)
#pragma unroll
            for (int j = 0; j < 4; j++) {
                int t = i * 4 + j;
#pragma unroll
                for (int e = 0; e < 4; e++) {
                    int rl = wm * 64 + i * 16 + g + ((e >> 1) << 3);
                    int cl = wn * 32 + j * 8 + 2 * tg + (e & 1);
                    if (rm_s[v][rl] && cm_s[v][cl])
                        smax[t][e] = fmaxf(smax[t][e], __expf(dot[t][e] * 5.0f));
                }
            }
    }

    // zero diagonal, store float2 pairs
#pragma unroll
    for (int i = 0; i < 4; i++)
#pragma unroll
        for (int j = 0; j < 4; j++) {
            int t = i * 4 + j;
#pragma unroll
            for (int h = 0; h < 2; h++) {
                int n   = rb * 128 + wm * 64 + i * 16 + g + h * 8;
                int col = cb * 128 + wn * 32 + j * 8 + 2 * tg;
                float v0 = smax[t][h * 2 + 0];
                float v1 = smax[t][h * 2 + 1];
                if (n == col)     v0 = 0.f;
                if (n == col + 1) v1 = 0.f;
                *(float2*)(g_s + (size_t)n * NN + col) = make_float2(v0, v1);
            }
        }
}

// ---------------- K3: rowsum + confi (row scan; deterministic) -------------
__global__ void k_rowstats(const int* __restrict__ mask, float* __restrict__ confi_out) {
    int n = blockIdx.x;
    int tid = threadIdx.x;
    const float4* srow = (const float4*)(g_s + (size_t)n * NN);
    float sum = 0.f, c0 = 0.f, c1 = 0.f, c2 = 0.f;
    for (int m4 = tid; m4 < NN / 4; m4 += 256) {
        float4 sv = srow[m4];
        float lv[4] = {sv.x, sv.y, sv.z, sv.w};
        const int* mp = mask + (size_t)m4 * 4 * NV;
#pragma unroll
        for (int k = 0; k < 4; k++) {
            sum += lv[k];
            float lg = 0.2f * __logf(lv[k] + 1e-9f);
            if (mp[k * NV + 0]) c0 = fmaxf(c0, lg);
            if (mp[k * NV + 1]) c1 = fmaxf(c1, lg);
            if (mp[k * NV + 2]) c2 = fmaxf(c2, lg);
        }
    }
    __shared__ float rs0[256], rs1[256], rs2[256], rs3[256];
    rs0[tid] = sum; rs1[tid] = c0; rs2[tid] = c1; rs3[tid] = c2;
    __syncthreads();
    for (int off = 128; off > 0; off >>= 1) {
        if (tid < off) {
            rs0[tid] += rs0[tid + off];
            rs1[tid] = fmaxf(rs1[tid], rs1[tid + off]);
            rs2[tid] = fmaxf(rs2[tid], rs2[tid + off]);
            rs3[tid] = fmaxf(rs3[tid], rs3[tid + off]);
        }
        __syncthreads();
    }
    if (tid == 0) {
        g_rowsum[n] = rs0[0];
        confi_out[0 * NN + n] = fminf(rs1[0], 1.0f);
        confi_out[1 * NN + n] = fminf(rs2[0], 1.0f);
        confi_out[2 * NN + n] = fminf(rs3[0], 1.0f);
    }
}

// ---------------- K4: new_x = (s/rowsum) @ xb_v, blend, expand to Z --------
// tf32 mma.sync. Block tile 64 rows x 128 h, 8 warps (2x4), warp tile 32x32.
// grid (64, 2, 3) = 384 blocks. Z written from the epilogue (float2, 32B sectors).
__global__ __launch_bounds__(256, 1) void k_newx_tc(const int* __restrict__ mask,
                                                    float* __restrict__ out) {
    int rb = blockIdx.x, hb = blockIdx.y, v = blockIdx.z;
    int h0 = hb * 128;
    int tid = threadIdx.x, lane = tid & 31, wid = tid >> 5;
    int wm = wid >> 2, wn = wid & 3;
    int g = lane >> 2, tg = lane & 3;

    __shared__ unsigned As[64 * 36];     // s tile  [row][k], pad 36
    __shared__ unsigned Bs[32 * 136];    // xb tile [k][h],  pad 136
    __shared__ float yns[CC * 128];

    for (int l = tid; l < CC * 128; l += 256)
        yns[l] = g_yn[(l >> 7) * HH + h0 + (l & 127)];

    const float* xb = g_xb + (size_t)v * NN * HH;
    float acc[8][4];
#pragma unroll
    for (int t = 0; t < 8; t++)
#pragma unroll
        for (int e = 0; e < 4; e++) acc[t][e] = 0.f;

    for (int m0 = 0; m0 < NN; m0 += 32) {
#pragma unroll
        for (int q = 0; q < 2; q++) {                  // A: 64x32
            int l = q * 256 + tid;
            int r = l >> 3, kq = l & 7;
            float4 f = *(const float4*)(g_s + (size_t)(rb * 64 + r) * NN + m0 + kq * 4);
            As[r * 36 + kq * 4 + 0] = f2tf(f.x);
            As[r * 36 + kq * 4 + 1] = f2tf(f.y);
            As[r * 36 + kq * 4 + 2] = f2tf(f.z);
            As[r * 36 + kq * 4 + 3] = f2tf(f.w);
        }
#pragma unroll
        for (int q = 0; q < 4; q++) {                  // B: 32k x 128h
            int l = q * 256 + tid;
            int kr = l >> 5, c4 = l & 31;
            float4 f = *(const float4*)(xb + (size_t)(m0 + kr) * HH + h0 + c4 * 4);
            Bs[kr * 136 + c4 * 4 + 0] = f2tf(f.x);
            Bs[kr * 136 + c4 * 4 + 1] = f2tf(f.y);
            Bs[kr * 136 + c4 * 4 + 2] = f2tf(f.z);
            Bs[kr * 136 + c4 * 4 + 3] = f2tf(f.w);
        }
        __syncthreads();
#pragma unroll
        for (int ks = 0; ks < 4; ks++) {
            int ca = ks * 8 + tg;
            unsigned a[2][4], b[4][2];
#pragma unroll
            for (int i = 0; i < 2; i++) {
                int r = wm * 32 + i * 16 + g;
                a[i][0] = As[r * 36 + ca];
                a[i][1] = As[(r + 8) * 36 + ca];
                a[i][2] = As[r * 36 + ca + 4];
                a[i][3] = As[(r + 8) * 36 + ca + 4];
            }
#pragma unroll
            for (int j = 0; j < 4; j++) {
                int c = wn * 32 + j * 8 + g;
                b[j][0] = Bs[(ks * 8 + tg) * 136 + c];
                b[j][1] = Bs[(ks * 8 + tg + 4) * 136 + c];
            }
#pragma unroll
            for (int i = 0; i < 2; i++)
#pragma unroll
                for (int j = 0; j < 4; j++)
                    mma_tf32(acc[i * 4 + j], a[i], b[j]);
        }
        __syncthreads();
    }

    // epilogue: rowsum scale, mask blend with xp, y_n expansion to Z
#pragma unroll
    for (int i = 0; i < 2; i++)
#pragma unroll
        for (int h = 0; h < 2; h++) {
            int n = rb * 64 + wm * 32 + i * 16 + g + h * 8;
            float rinv = 1.f / (g_rowsum[n] + 1e-9f);
            int mrow = mask[n * NV + v];
            float nx[8];
            if (mrow) {
                const float* xpr = g_xp + ((size_t)v * NN + n) * HH + h0;
#pragma unroll
                for (int j = 0; j < 4; j++) {
                    float2 p = *(const float2*)(xpr + wn * 32 + j * 8 + 2 * tg);
                    nx[j * 2]     = p.x;
                    nx[j * 2 + 1] = p.y;
                }
            } else {
#pragma unroll
                for (int j = 0; j < 4; j++) {
                    nx[j * 2]     = acc[i * 4 + j][h * 2]     * rinv;
                    nx[j * 2 + 1] = acc[i * 4 + j][h * 2 + 1] * rinv;
                }
            }
            size_t zbase = (size_t)(v * NN + n) * (CC * HH) + h0;
#pragma unroll
            for (int c = 0; c < CC; c++) {
                size_t rowb = zbase + (size_t)c * HH;
#pragma unroll
                for (int j = 0; j < 4; j++) {
                    int col = wn * 32 + j * 8 + 2 * tg;
                    float2 yv = *(const float2*)&yns[c * 128 + col];
                    *(float2*)(out + rowb + col) =
                        make_float2(nx[j * 2] * yv.x, nx[j * 2 + 1] * yv.y);
                }
            }
        }
}

// ---------------- launch ----------------------------------------------------
extern "C" void kernel_launch(void* const* d_in, const int* in_sizes, int n_in,
                              void* d_out, int out_size) {
    ProjPtrs P{};
    const float* yv  = nullptr;
    const float* Wy  = nullptr;
    const float* byp = nullptr;
    const int*   mask = nullptr;
    int nx = 0, nW = 0, nb = 0;
    for (int i = 0; i < n_in; i++) {
        int s = in_sizes[i];
        if      (s == NN * DD)  { if (nx < NV) P.x[nx++] = (const float*)d_in[i]; }
        else if (s == HH * DD)  { if (nW < NV) P.W[nW++] = (const float*)d_in[i]; }
        else if (s == CC * DYY) yv = (const float*)d_in[i];
        else if (s == HH * DYY) Wy = (const float*)d_in[i];
        else if (s == NN * NV)  mask = (const int*)d_in[i];
        else if (s == HH) {
            if (nb < NV) P.b[nb++] = (const float*)d_in[i];
            else         byp = (const float*)d_in[i];
        }
    }
    P.mask = mask;
    float* out = (float*)d_out;
    float* confi_out = out + ((size_t)out_size - (size_t)NV * NN);

    k_yn      <<<CC, HH>>>(yv, Wy, byp);
    k_proj    <<<dim3(NN / 64, NV), 256>>>(P);
    k_smat_tc <<<dim3(NN / 128, NN / 128), 256>>>(mask);
    k_rowstats<<<NN, 256>>>(mask, confi_out);
    k_newx_tc <<<dim3(NN / 64, HH / 128, NV), 256>>>(mask, out);
}

// round 8
// speedup vs baseline: 2.9444x; 1.3545x over previous
#include <cuda_runtime.h>
#include <cuda_bf16.h>

#define NV  3
#define NN  4096
#define HH  256
#define CC  20
#define DYY 300
#define DD  512

// ---------------- scratch (static device globals; no runtime allocation) ----
__device__ float g_xp[(size_t)NV * NN * HH];   // leaky(x@W^T+b)          (fp32)
__device__ float g_xq[(size_t)NV * NN * HH];   // normalized, tf32-rounded
__device__ float g_xb[(size_t)NV * NN * HH];   // xp*colmask, tf32-rounded
__device__ float g_s [(size_t)NN * NN];        // max_v exp(...), tf32-rounded
__device__ float g_rowsum[NN];
__device__ float g_yn[CC * HH];

struct ProjPtrs {
    const float* x[NV];
    const float* W[NV];
    const float* b[NV];
    const int*   mask;
};

// ---------------- helpers ---------------------------------------------------
__device__ __forceinline__ unsigned f2tf(float f) {
    unsigned u;
    asm("cvt.rna.tf32.f32 %0, %1;" : "=r"(u) : "f"(f));
    return u;
}
__device__ __forceinline__ float f2tf_f(float f) { return __uint_as_float(f2tf(f)); }

__device__ __forceinline__ void mma_tf32(float* d, const unsigned* a, const unsigned* b) {
    asm volatile(
        "mma.sync.aligned.m16n8k8.row.col.f32.tf32.tf32.f32 "
        "{%0,%1,%2,%3},{%4,%5,%6,%7},{%8,%9},{%0,%1,%2,%3};"
        : "+f"(d[0]), "+f"(d[1]), "+f"(d[2]), "+f"(d[3])
        : "r"(a[0]), "r"(a[1]), "r"(a[2]), "r"(a[3]), "r"(b[0]), "r"(b[1]));
}

__device__ __forceinline__ void cp16(float* dst, const float* src) {
    unsigned d = (unsigned)__cvta_generic_to_shared(dst);
    asm volatile("cp.async.cg.shared.global [%0], [%1], 16;" :: "r"(d), "l"(src) : "memory");
}
#define CP_COMMIT() asm volatile("cp.async.commit_group;" ::: "memory")
#define CP_WAIT0()  asm volatile("cp.async.wait_group 0;" ::: "memory")

// ---------------- K0: y_n = sigmoid(y @ Wy^T + by) --------------------------
__global__ void k_yn(const float* __restrict__ y,
                     const float* __restrict__ Wy,
                     const float* __restrict__ by) {
    int c = blockIdx.x;
    int h = threadIdx.x;
    __shared__ float ys[DYY];
    for (int d = threadIdx.x; d < DYY; d += blockDim.x) ys[d] = y[c * DYY + d];
    __syncthreads();
    const float* wr = Wy + (size_t)h * DYY;
    float acc = 0.f;
#pragma unroll 4
    for (int d = 0; d < DYY; d++) acc = fmaf(ys[d], wr[d], acc);
    acc += by[h];
    g_yn[c * HH + h] = 1.f / (1.f + __expf(-acc));
}

// ---------------- K1: xp / xq / xb  (xq, xb stored pre-rounded to tf32) -----
__global__ __launch_bounds__(256, 1) void k_proj(ProjPtrs P) {
    int v  = blockIdx.y;
    int rb = blockIdx.x;
    int tid = threadIdx.x;
    int ty = tid >> 5;
    int tx = tid & 31;

    __shared__ float As[64 * 33];
    __shared__ float Bs[32 * 260];

    const float* xv = P.x[v];
    const float* Wv = P.W[v];

    float acc[8][8];
#pragma unroll
    for (int i = 0; i < 8; i++)
#pragma unroll
        for (int j = 0; j < 8; j++) acc[i][j] = 0.f;

    for (int k0 = 0; k0 < DD; k0 += 32) {
#pragma unroll
        for (int q = 0; q < 2; q++) {
            int l = tid * 2 + q;
            int r = l >> 3, kq = l & 7;
            float4 f = *(const float4*)(xv + (size_t)(rb * 64 + r) * DD + k0 + kq * 4);
            As[r * 33 + kq * 4 + 0] = f.x;
            As[r * 33 + kq * 4 + 1] = f.y;
            As[r * 33 + kq * 4 + 2] = f.z;
            As[r * 33 + kq * 4 + 3] = f.w;
        }
#pragma unroll
        for (int q = 0; q < 8; q++) {
            int l = tid * 8 + q;
            int h = l >> 3, kq = l & 7;
            float4 f = *(const float4*)(Wv + (size_t)h * DD + k0 + kq * 4);
            Bs[(kq * 4 + 0) * 260 + h] = f.x;
            Bs[(kq * 4 + 1) * 260 + h] = f.y;
            Bs[(kq * 4 + 2) * 260 + h] = f.z;
            Bs[(kq * 4 + 3) * 260 + h] = f.w;
        }
        __syncthreads();
#pragma unroll
        for (int kk = 0; kk < 32; kk++) {
            float a[8];
#pragma unroll
            for (int i = 0; i < 8; i++) a[i] = As[(ty * 8 + i) * 33 + kk];
            float4 b0 = *(const float4*)&Bs[kk * 260 + tx * 8];
            float4 b1 = *(const float4*)&Bs[kk * 260 + tx * 8 + 4];
            float bb[8] = {b0.x, b0.y, b0.z, b0.w, b1.x, b1.y, b1.z, b1.w};
#pragma unroll
            for (int i = 0; i < 8; i++)
#pragma unroll
                for (int j = 0; j < 8; j++)
                    acc[i][j] = fmaf(a[i], bb[j], acc[i][j]);
        }
        __syncthreads();
    }

    float bb[8];
#pragma unroll
    for (int j = 0; j < 8; j++) bb[j] = P.b[v][tx * 8 + j];
#pragma unroll
    for (int i = 0; i < 8; i++)
#pragma unroll
        for (int j = 0; j < 8; j++) {
            float t = acc[i][j] + bb[j];
            acc[i][j] = (t >= 0.f) ? t : 0.1f * t;
        }

#pragma unroll
    for (int i = 0; i < 8; i++) {
        float ss = 0.f;
#pragma unroll
        for (int j = 0; j < 8; j++) ss = fmaf(acc[i][j], acc[i][j], ss);
#pragma unroll
        for (int off = 16; off > 0; off >>= 1)
            ss += __shfl_xor_sync(0xFFFFFFFFu, ss, off);
        float rinv = 1.f / fmaxf(sqrtf(ss), 1e-12f);

        int n = rb * 64 + ty * 8 + i;
        float mrow = (float)P.mask[n * NV + v];
        size_t base = ((size_t)v * NN + n) * HH + tx * 8;

        float p[8];
#pragma unroll
        for (int j = 0; j < 8; j++) p[j] = acc[i][j];
        *(float4*)(g_xp + base)     = make_float4(p[0], p[1], p[2], p[3]);
        *(float4*)(g_xp + base + 4) = make_float4(p[4], p[5], p[6], p[7]);

        float q[8], m[8];
#pragma unroll
        for (int j = 0; j < 8; j++) {
            q[j] = f2tf_f(p[j] * rinv);     // tf32-rounded normalized
            m[j] = f2tf_f(p[j] * mrow);     // tf32-rounded col-masked
        }
        *(float4*)(g_xq + base)     = make_float4(q[0], q[1], q[2], q[3]);
        *(float4*)(g_xq + base + 4) = make_float4(q[4], q[5], q[6], q[7]);
        *(float4*)(g_xb + base)     = make_float4(m[0], m[1], m[2], m[3]);
        *(float4*)(g_xb + base + 4) = make_float4(m[4], m[5], m[6], m[7]);
    }
}

// ---------------- K2: s = max_v exp(xq_v @ xq_v^T / beta)*masks, diag=0 ----
// tf32 mma, cp.async double-buffered. Block 128x128, 8 warps, warp 64x32.
// Flattened pipeline over 24 chunks (3 views x 8 k-chunks).
#define SMAT_BUF (128 * 36)
__global__ __launch_bounds__(256, 1) void k_smat_tc(const int* __restrict__ mask) {
    int cb = blockIdx.x, rb = blockIdx.y;
    int tid = threadIdx.x, lane = tid & 31, wid = tid >> 5;
    int wm = wid >> 2, wn = wid & 3;
    int g = lane >> 2, tg = lane & 3;

    extern __shared__ float dyn[];
    float* Abuf = dyn;                     // [2][128*36]
    float* Bbuf = dyn + 2 * SMAT_BUF;      // [2][128*36]

    __shared__ int rm_s[NV][128], cm_s[NV][128];
    for (int l = tid; l < 128; l += 256) {
#pragma unroll
        for (int v = 0; v < NV; v++) {
            rm_s[v][l] = mask[(rb * 128 + l) * NV + v];
            cm_s[v][l] = mask[(cb * 128 + l) * NV + v];
        }
    }

    auto load_chunk = [&](int c, int buf) {
        int v = c >> 3, k0 = (c & 7) * 32;
        const float* xq = g_xq + (size_t)v * NN * HH;
        float* Ab = Abuf + buf * SMAT_BUF;
        float* Bb = Bbuf + buf * SMAT_BUF;
#pragma unroll
        for (int q = 0; q < 4; q++) {
            int l = q * 256 + tid;
            int r = l >> 3, kq = l & 7;
            cp16(Ab + r * 36 + kq * 4, xq + (size_t)(rb * 128 + r) * HH + k0 + kq * 4);
            cp16(Bb + r * 36 + kq * 4, xq + (size_t)(cb * 128 + r) * HH + k0 + kq * 4);
        }
        CP_COMMIT();
    };

    float smax[16][4];
#pragma unroll
    for (int t = 0; t < 16; t++)
#pragma unroll
        for (int e = 0; e < 4; e++) smax[t][e] = 0.f;

    float dot[16][4];
#pragma unroll
    for (int t = 0; t < 16; t++)
#pragma unroll
        for (int e = 0; e < 4; e++) dot[t][e] = 0.f;

    load_chunk(0, 0);

    for (int c = 0; c < 24; c++) {
        CP_WAIT0();
        __syncthreads();
        if (c < 23) load_chunk(c + 1, (c + 1) & 1);

        const unsigned* As = (const unsigned*)(Abuf + (c & 1) * SMAT_BUF);
        const unsigned* Bs = (const unsigned*)(Bbuf + (c & 1) * SMAT_BUF);
#pragma unroll
        for (int ks = 0; ks < 4; ks++) {
            int ca = ks * 8 + tg;
            unsigned a[4][4], b[4][2];
#pragma unroll
            for (int i = 0; i < 4; i++) {
                int r = wm * 64 + i * 16 + g;
                a[i][0] = As[r * 36 + ca];
                a[i][1] = As[(r + 8) * 36 + ca];
                a[i][2] = As[r * 36 + ca + 4];
                a[i][3] = As[(r + 8) * 36 + ca + 4];
            }
#pragma unroll
            for (int j = 0; j < 4; j++) {
                int cc = wn * 32 + j * 8 + g;
                b[j][0] = Bs[cc * 36 + ca];
                b[j][1] = Bs[cc * 36 + ca + 4];
            }
#pragma unroll
            for (int i = 0; i < 4; i++)
#pragma unroll
                for (int j = 0; j < 4; j++)
                    mma_tf32(dot[i * 4 + j], a[i], b[j]);
        }

        if ((c & 7) == 7) {                 // view boundary: merge + reset
            int v = c >> 3;
#pragma unroll
            for (int i = 0; i < 4; i++)
#pragma unroll
                for (int j = 0; j < 4; j++) {
                    int t = i * 4 + j;
#pragma unroll
                    for (int e = 0; e < 4; e++) {
                        int rl = wm * 64 + i * 16 + g + ((e >> 1) << 3);
                        int cl = wn * 32 + j * 8 + 2 * tg + (e & 1);
                        if (rm_s[v][rl] && cm_s[v][cl])
                            smax[t][e] = fmaxf(smax[t][e], __expf(dot[t][e] * 5.0f));
                        dot[t][e] = 0.f;
                    }
                }
        }
    }

    // zero diagonal, round to tf32, store float2 pairs
#pragma unroll
    for (int i = 0; i < 4; i++)
#pragma unroll
        for (int j = 0; j < 4; j++) {
            int t = i * 4 + j;
#pragma unroll
            for (int h = 0; h < 2; h++) {
                int n   = rb * 128 + wm * 64 + i * 16 + g + h * 8;
                int col = cb * 128 + wn * 32 + j * 8 + 2 * tg;
                float v0 = f2tf_f(smax[t][h * 2 + 0]);
                float v1 = f2tf_f(smax[t][h * 2 + 1]);
                if (n == col)     v0 = 0.f;
                if (n == col + 1) v1 = 0.f;
                *(float2*)(g_s + (size_t)n * NN + col) = make_float2(v0, v1);
            }
        }
}

// ---------------- K3: rowsum + confi ----------------------------------------
__global__ void k_rowstats(const int* __restrict__ mask, float* __restrict__ confi_out) {
    int n = blockIdx.x;
    int tid = threadIdx.x;
    const float4* srow = (const float4*)(g_s + (size_t)n * NN);
    float sum = 0.f, c0 = 0.f, c1 = 0.f, c2 = 0.f;
    for (int m4 = tid; m4 < NN / 4; m4 += 256) {
        float4 sv = srow[m4];
        float lv[4] = {sv.x, sv.y, sv.z, sv.w};
        const int* mp = mask + (size_t)m4 * 4 * NV;
#pragma unroll
        for (int k = 0; k < 4; k++) {
            sum += lv[k];
            float lg = 0.2f * __logf(lv[k] + 1e-9f);
            if (mp[k * NV + 0]) c0 = fmaxf(c0, lg);
            if (mp[k * NV + 1]) c1 = fmaxf(c1, lg);
            if (mp[k * NV + 2]) c2 = fmaxf(c2, lg);
        }
    }
    __shared__ float rs0[256], rs1[256], rs2[256], rs3[256];
    rs0[tid] = sum; rs1[tid] = c0; rs2[tid] = c1; rs3[tid] = c2;
    __syncthreads();
    for (int off = 128; off > 0; off >>= 1) {
        if (tid < off) {
            rs0[tid] += rs0[tid + off];
            rs1[tid] = fmaxf(rs1[tid], rs1[tid + off]);
            rs2[tid] = fmaxf(rs2[tid], rs2[tid + off]);
            rs3[tid] = fmaxf(rs3[tid], rs3[tid + off]);
        }
        __syncthreads();
    }
    if (tid == 0) {
        g_rowsum[n] = rs0[0];
        confi_out[0 * NN + n] = fminf(rs1[0], 1.0f);
        confi_out[1 * NN + n] = fminf(rs2[0], 1.0f);
        confi_out[2 * NN + n] = fminf(rs3[0], 1.0f);
    }
}

// ---------------- K4: new_x = (s/rowsum) @ xb_v -> blend -> Z ---------------
// tf32 mma, cp.async double-buffered. Block 64x128, 8 warps, warp 32x32.
#define NEWX_ABUF (64 * 36)
#define NEWX_BBUF (32 * 136)
__global__ __launch_bounds__(256, 2) void k_newx_tc(const int* __restrict__ mask,
                                                    float* __restrict__ out) {
    int rb = blockIdx.x, hb = blockIdx.y, v = blockIdx.z;
    int h0 = hb * 128;
    int tid = threadIdx.x, lane = tid & 31, wid = tid >> 5;
    int wm = wid >> 2, wn = wid & 3;
    int g = lane >> 2, tg = lane & 3;

    extern __shared__ float dyn[];
    float* Abuf = dyn;                       // [2][64*36]
    float* Bbuf = dyn + 2 * NEWX_ABUF;       // [2][32*136]
    __shared__ float yns[CC * 128];

    for (int l = tid; l < CC * 128; l += 256)
        yns[l] = g_yn[(l >> 7) * HH + h0 + (l & 127)];

    const float* xb = g_xb + (size_t)v * NN * HH;

    auto load_chunk = [&](int c, int buf) {
        int m0 = c * 32;
        float* Ab = Abuf + buf * NEWX_ABUF;
        float* Bb = Bbuf + buf * NEWX_BBUF;
#pragma unroll
        for (int q = 0; q < 2; q++) {
            int l = q * 256 + tid;
            int r = l >> 3, kq = l & 7;
            cp16(Ab + r * 36 + kq * 4, g_s + (size_t)(rb * 64 + r) * NN + m0 + kq * 4);
        }
#pragma unroll
        for (int q = 0; q < 4; q++) {
            int l = q * 256 + tid;
            int kr = l >> 5, c4 = l & 31;
            cp16(Bb + kr * 136 + c4 * 4, xb + (size_t)(m0 + kr) * HH + h0 + c4 * 4);
        }
        CP_COMMIT();
    };

    float acc[8][4];
#pragma unroll
    for (int t = 0; t < 8; t++)
#pragma unroll
        for (int e = 0; e < 4; e++) acc[t][e] = 0.f;

    load_chunk(0, 0);

    for (int c = 0; c < NN / 32; c++) {
        CP_WAIT0();
        __syncthreads();
        if (c < NN / 32 - 1) load_chunk(c + 1, (c + 1) & 1);

        const unsigned* As = (const unsigned*)(Abuf + (c & 1) * NEWX_ABUF);
        const unsigned* Bs = (const unsigned*)(Bbuf + (c & 1) * NEWX_BBUF);
#pragma unroll
        for (int ks = 0; ks < 4; ks++) {
            int ca = ks * 8 + tg;
            unsigned a[2][4], b[4][2];
#pragma unroll
            for (int i = 0; i < 2; i++) {
                int r = wm * 32 + i * 16 + g;
                a[i][0] = As[r * 36 + ca];
                a[i][1] = As[(r + 8) * 36 + ca];
                a[i][2] = As[r * 36 + ca + 4];
                a[i][3] = As[(r + 8) * 36 + ca + 4];
            }
#pragma unroll
            for (int j = 0; j < 4; j++) {
                int cc = wn * 32 + j * 8 + g;
                b[j][0] = Bs[(ks * 8 + tg) * 136 + cc];
                b[j][1] = Bs[(ks * 8 + tg + 4) * 136 + cc];
            }
#pragma unroll
            for (int i = 0; i < 2; i++)
#pragma unroll
                for (int j = 0; j < 4; j++)
                    mma_tf32(acc[i * 4 + j], a[i], b[j]);
        }
    }

    // epilogue: rowsum scale, mask blend with xp, y_n expansion to Z
#pragma unroll
    for (int i = 0; i < 2; i++)
#pragma unroll
        for (int h = 0; h < 2; h++) {
            int n = rb * 64 + wm * 32 + i * 16 + g + h * 8;
            float rinv = 1.f / (g_rowsum[n] + 1e-9f);
            int mrow = mask[n * NV + v];
            float nx[8];
            if (mrow) {
                const float* xpr = g_xp + ((size_t)v * NN + n) * HH + h0;
#pragma unroll
                for (int j = 0; j < 4; j++) {
                    float2 p = *(const float2*)(xpr + wn * 32 + j * 8 + 2 * tg);
                    nx[j * 2]     = p.x;
                    nx[j * 2 + 1] = p.y;
                }
            } else {
#pragma unroll
                for (int j = 0; j < 4; j++) {
                    nx[j * 2]     = acc[i * 4 + j][h * 2]     * rinv;
                    nx[j * 2 + 1] = acc[i * 4 + j][h * 2 + 1] * rinv;
                }
            }
            size_t zbase = (size_t)(v * NN + n) * (CC * HH) + h0;
#pragma unroll
            for (int c = 0; c < CC; c++) {
                size_t rowb = zbase + (size_t)c * HH;
#pragma unroll
                for (int j = 0; j < 4; j++) {
                    int col = wn * 32 + j * 8 + 2 * tg;
                    float2 yv = *(const float2*)&yns[c * 128 + col];
                    *(float2*)(out + rowb + col) =
                        make_float2(nx[j * 2] * yv.x, nx[j * 2 + 1] * yv.y);
                }
            }
        }
}

// ---------------- launch ----------------------------------------------------
extern "C" void kernel_launch(void* const* d_in, const int* in_sizes, int n_in,
                              void* d_out, int out_size) {
    ProjPtrs P{};
    const float* yv  = nullptr;
    const float* Wy  = nullptr;
    const float* byp = nullptr;
    const int*   mask = nullptr;
    int nx = 0, nW = 0, nb = 0;
    for (int i = 0; i < n_in; i++) {
        int s = in_sizes[i];
        if      (s == NN * DD)  { if (nx < NV) P.x[nx++] = (const float*)d_in[i]; }
        else if (s == HH * DD)  { if (nW < NV) P.W[nW++] = (const float*)d_in[i]; }
        else if (s == CC * DYY) yv = (const float*)d_in[i];
        else if (s == HH * DYY) Wy = (const float*)d_in[i];
        else if (s == NN * NV)  mask = (const int*)d_in[i];
        else if (s == HH) {
            if (nb < NV) P.b[nb++] = (const float*)d_in[i];
            else         byp = (const float*)d_in[i];
        }
    }
    P.mask = mask;
    float* out = (float*)d_out;
    float* confi_out = out + ((size_t)out_size - (size_t)NV * NN);

    const int smat_dyn = 4 * SMAT_BUF * (int)sizeof(float);                 // 73728
    const int newx_dyn = (2 * NEWX_ABUF + 2 * NEWX_BBUF) * (int)sizeof(float); // 53248
    cudaFuncSetAttribute(k_smat_tc, cudaFuncAttributeMaxDynamicSharedMemorySize, smat_dyn);
    cudaFuncSetAttribute(k_newx_tc, cudaFuncAttributeMaxDynamicSharedMemorySize, newx_dyn);

    k_yn      <<<CC, HH>>>(yv, Wy, byp);
    k_proj    <<<dim3(NN / 64, NV), 256>>>(P);
    k_smat_tc <<<dim3(NN / 128, NN / 128), 256, smat_dyn>>>(mask);
    k_rowstats<<<NN, 256>>>(mask, confi_out);
    k_newx_tc <<<dim3(NN / 64, HH / 128, NV), 256, newx_dyn>>>(mask, out);
}

// round 9
// speedup vs baseline: 3.1545x; 1.0714x over previous
#include <cuda_runtime.h>
#include <cuda_bf16.h>

#define NV  3
#define NN  4096
#define HH  256
#define CC  20
#define DYY 300
#define DD  512

// ---------------- scratch (static device globals) ---------------------------
__device__ float g_xp[(size_t)NV * NN * HH];   // leaky(x@W^T+b)  (fp32)
__device__ float g_xq[(size_t)NV * NN * HH];   // normalized, tf32-rounded
__device__ float g_xb[(size_t)NV * NN * HH];   // xp*colmask, tf32-rounded
__device__ float g_s [(size_t)NN * NN];        // max_v exp(...), tf32-rounded
__device__ float g_rowsum[NN];
__device__ float g_yn[CC * HH];
__device__ float g_xr[(size_t)NV * NN * DD];   // x rounded to tf32
__device__ float g_wr[(size_t)NV * HH * DD];   // W rounded to tf32

struct ProjPtrs {
    const float* b[NV];
    const int*   mask;
};
struct RoundPtrs {
    const float* x[NV];
    const float* W[NV];
};

// ---------------- helpers ---------------------------------------------------
__device__ __forceinline__ unsigned f2tf(float f) {
    unsigned u;
    asm("cvt.rna.tf32.f32 %0, %1;" : "=r"(u) : "f"(f));
    return u;
}
__device__ __forceinline__ float f2tf_f(float f) { return __uint_as_float(f2tf(f)); }

__device__ __forceinline__ void mma_tf32(float* d, const unsigned* a, const unsigned* b) {
    asm volatile(
        "mma.sync.aligned.m16n8k8.row.col.f32.tf32.tf32.f32 "
        "{%0,%1,%2,%3},{%4,%5,%6,%7},{%8,%9},{%0,%1,%2,%3};"
        : "+f"(d[0]), "+f"(d[1]), "+f"(d[2]), "+f"(d[3])
        : "r"(a[0]), "r"(a[1]), "r"(a[2]), "r"(a[3]), "r"(b[0]), "r"(b[1]));
}

__device__ __forceinline__ void ldsm4(unsigned* r, const void* p) {
    unsigned a = (unsigned)__cvta_generic_to_shared(p);
    asm volatile("ldmatrix.sync.aligned.m8n8.x4.shared.b16 {%0,%1,%2,%3}, [%4];"
                 : "=r"(r[0]), "=r"(r[1]), "=r"(r[2]), "=r"(r[3]) : "r"(a));
}

__device__ __forceinline__ void cp16(float* dst, const float* src) {
    unsigned d = (unsigned)__cvta_generic_to_shared(dst);
    asm volatile("cp.async.cg.shared.global [%0], [%1], 16;" :: "r"(d), "l"(src) : "memory");
}
#define CP_COMMIT() asm volatile("cp.async.commit_group;" ::: "memory")
#define CP_WAIT0()  asm volatile("cp.async.wait_group 0;" ::: "memory")

// ---------------- K-1: round x, W to tf32 in gmem ---------------------------
__global__ void k_round(RoundPtrs R) {
    const int XN4 = NN * DD / 4, WN4 = HH * DD / 4;
    int idx = blockIdx.x * 256 + threadIdx.x;
    float4 f;
    float* dst;
    if (idx < 3 * XN4) {
        int v = idx / XN4, r = idx % XN4;
        f = ((const float4*)R.x[v])[r];
        dst = g_xr + (size_t)v * NN * DD + (size_t)r * 4;
    } else if (idx < 3 * XN4 + 3 * WN4) {
        int t = idx - 3 * XN4;
        int v = t / WN4, r = t % WN4;
        f = ((const float4*)R.W[v])[r];
        dst = g_wr + (size_t)v * HH * DD + (size_t)r * 4;
    } else return;
    f.x = f2tf_f(f.x); f.y = f2tf_f(f.y); f.z = f2tf_f(f.z); f.w = f2tf_f(f.w);
    *(float4*)dst = f;
}

// ---------------- K0: y_n = sigmoid(y @ Wy^T + by) --------------------------
__global__ void k_yn(const float* __restrict__ y,
                     const float* __restrict__ Wy,
                     const float* __restrict__ by) {
    int c = blockIdx.x;
    int h = threadIdx.x;
    __shared__ float ys[DYY];
    for (int d = threadIdx.x; d < DYY; d += blockDim.x) ys[d] = y[c * DYY + d];
    __syncthreads();
    const float* wr = Wy + (size_t)h * DYY;
    float acc = 0.f;
#pragma unroll 4
    for (int d = 0; d < DYY; d++) acc = fmaf(ys[d], wr[d], acc);
    acc += by[h];
    g_yn[c * HH + h] = 1.f / (1.f + __expf(-acc));
}

// ---------------- K1: tensor-core proj: xp / xq / xb ------------------------
// Block 64 rows x 256 cols (full H). 8 warps 2x4: warp 32x64.
// A = x (rows [m][k]), B = W (rows [h][k]) both pre-rounded tf32, cp.async.
#define PROJ_ABUF (64 * 36)
#define PROJ_BBUF (256 * 36)
__global__ __launch_bounds__(256, 1) void k_proj_tc(ProjPtrs P) {
    int v = blockIdx.y, rb = blockIdx.x;
    int tid = threadIdx.x, lane = tid & 31, wid = tid >> 5;
    int wm = wid >> 2, wn = wid & 3;
    int g = lane >> 2, tg = lane & 3;

    extern __shared__ float dyn[];
    float* Abuf = dyn;                          // [2][64*36]
    float* Bbuf = dyn + 2 * PROJ_ABUF;          // [2][256*36]
    __shared__ float ss[4][64];

    const float* xr = g_xr + (size_t)v * NN * DD;
    const float* wr = g_wr + (size_t)v * HH * DD;

    auto load_chunk = [&](int c, int buf) {
        int k0 = c * 32;
        float* A = Abuf + buf * PROJ_ABUF;
        float* B = Bbuf + buf * PROJ_BBUF;
#pragma unroll
        for (int q = 0; q < 2; q++) {
            int l = q * 256 + tid;
            int r = l >> 3, kq = l & 7;
            cp16(A + r * 36 + kq * 4, xr + (size_t)(rb * 64 + r) * DD + k0 + kq * 4);
        }
#pragma unroll
        for (int q = 0; q < 8; q++) {
            int l = q * 256 + tid;
            int r = l >> 3, kq = l & 7;
            cp16(B + r * 36 + kq * 4, wr + (size_t)r * DD + k0 + kq * 4);
        }
        CP_COMMIT();
    };

    float acc[16][4];
#pragma unroll
    for (int t = 0; t < 16; t++)
#pragma unroll
        for (int e = 0; e < 4; e++) acc[t][e] = 0.f;

    load_chunk(0, 0);
    for (int c = 0; c < DD / 32; c++) {
        CP_WAIT0();
        __syncthreads();
        if (c < DD / 32 - 1) load_chunk(c + 1, (c + 1) & 1);
        const float* A = Abuf + (c & 1) * PROJ_ABUF;
        const float* B = Bbuf + (c & 1) * PROJ_BBUF;
#pragma unroll
        for (int ks = 0; ks < 4; ks++) {
            unsigned a[2][4], b[8][2];
#pragma unroll
            for (int i = 0; i < 2; i++)
                ldsm4(a[i], A + (wm * 32 + i * 16 + (lane & 15)) * 36
                              + ks * 8 + ((lane >> 4) & 1) * 4);
#pragma unroll
            for (int jp = 0; jp < 4; jp++) {
                unsigned t[4];
                ldsm4(t, B + (wn * 64 + jp * 16 + (lane & 7) + ((lane >> 4) & 1) * 8) * 36
                           + ks * 8 + ((lane >> 3) & 1) * 4);
                b[jp * 2][0] = t[0]; b[jp * 2][1] = t[1];
                b[jp * 2 + 1][0] = t[2]; b[jp * 2 + 1][1] = t[3];
            }
#pragma unroll
            for (int i = 0; i < 2; i++)
#pragma unroll
                for (int j = 0; j < 8; j++)
                    mma_tf32(acc[i * 8 + j], a[i], b[j]);
        }
    }

    // epilogue: bias + leaky (in place), per-row sumsq, norm, 3 outputs
    float bcol[16];
#pragma unroll
    for (int j = 0; j < 8; j++) {
        bcol[j * 2]     = P.b[v][wn * 64 + j * 8 + 2 * tg];
        bcol[j * 2 + 1] = P.b[v][wn * 64 + j * 8 + 2 * tg + 1];
    }
    float ssq[4];
#pragma unroll
    for (int i = 0; i < 2; i++)
#pragma unroll
        for (int hh = 0; hh < 2; hh++) {
            float s = 0.f;
#pragma unroll
            for (int j = 0; j < 8; j++)
#pragma unroll
                for (int e = 0; e < 2; e++) {
                    float t = acc[i * 8 + j][hh * 2 + e] + bcol[j * 2 + e];
                    t = (t >= 0.f) ? t : 0.1f * t;
                    acc[i * 8 + j][hh * 2 + e] = t;
                    s = fmaf(t, t, s);
                }
            ssq[i * 2 + hh] = s;
        }
#pragma unroll
    for (int r4 = 0; r4 < 4; r4++) {
        ssq[r4] += __shfl_xor_sync(0xFFFFFFFFu, ssq[r4], 1);
        ssq[r4] += __shfl_xor_sync(0xFFFFFFFFu, ssq[r4], 2);
    }
    if (tg == 0) {
#pragma unroll
        for (int i = 0; i < 2; i++)
#pragma unroll
            for (int hh = 0; hh < 2; hh++)
                ss[wn][wm * 32 + i * 16 + hh * 8 + g] = ssq[i * 2 + hh];
    }
    __syncthreads();
#pragma unroll
    for (int i = 0; i < 2; i++)
#pragma unroll
        for (int hh = 0; hh < 2; hh++) {
            int lr = wm * 32 + i * 16 + hh * 8 + g;
            int n = rb * 64 + lr;
            float tot = (ss[0][lr] + ss[1][lr]) + (ss[2][lr] + ss[3][lr]);
            float rinv = 1.f / fmaxf(sqrtf(tot), 1e-12f);
            float mrow = (float)P.mask[n * NV + v];
            size_t base = ((size_t)v * NN + n) * HH;
#pragma unroll
            for (int j = 0; j < 8; j++) {
                int col = wn * 64 + j * 8 + 2 * tg;
                float p0 = acc[i * 8 + j][hh * 2];
                float p1 = acc[i * 8 + j][hh * 2 + 1];
                *(float2*)(g_xp + base + col) = make_float2(p0, p1);
                *(float2*)(g_xq + base + col) =
                    make_float2(f2tf_f(p0 * rinv), f2tf_f(p1 * rinv));
                *(float2*)(g_xb + base + col) =
                    make_float2(f2tf_f(p0 * mrow), f2tf_f(p1 * mrow));
            }
        }
}

// ---------------- K2: s = max_v exp(xq_v @ xq_v^T / beta)*masks, diag=0 ----
// Block 128x128, 8 warps 2x4, warp 64x32, cp.async double-buffered, ldmatrix.
#define SMAT_BUF (128 * 36)
__global__ __launch_bounds__(256, 1) void k_smat_tc(const int* __restrict__ mask) {
    int cb = blockIdx.x, rb = blockIdx.y;
    int tid = threadIdx.x, lane = tid & 31, wid = tid >> 5;
    int wm = wid >> 2, wn = wid & 3;
    int g = lane >> 2, tg = lane & 3;

    extern __shared__ float dyn[];
    float* Abuf = dyn;
    float* Bbuf = dyn + 2 * SMAT_BUF;

    __shared__ int rm_s[NV][128], cm_s[NV][128];
    for (int l = tid; l < 128; l += 256) {
#pragma unroll
        for (int v = 0; v < NV; v++) {
            rm_s[v][l] = mask[(rb * 128 + l) * NV + v];
            cm_s[v][l] = mask[(cb * 128 + l) * NV + v];
        }
    }

    auto load_chunk = [&](int c, int buf) {
        int v = c >> 3, k0 = (c & 7) * 32;
        const float* xq = g_xq + (size_t)v * NN * HH;
        float* Ab = Abuf + buf * SMAT_BUF;
        float* Bb = Bbuf + buf * SMAT_BUF;
#pragma unroll
        for (int q = 0; q < 4; q++) {
            int l = q * 256 + tid;
            int r = l >> 3, kq = l & 7;
            cp16(Ab + r * 36 + kq * 4, xq + (size_t)(rb * 128 + r) * HH + k0 + kq * 4);
            cp16(Bb + r * 36 + kq * 4, xq + (size_t)(cb * 128 + r) * HH + k0 + kq * 4);
        }
        CP_COMMIT();
    };

    float smax[16][4], dot[16][4];
#pragma unroll
    for (int t = 0; t < 16; t++)
#pragma unroll
        for (int e = 0; e < 4; e++) { smax[t][e] = 0.f; dot[t][e] = 0.f; }

    load_chunk(0, 0);

    for (int c = 0; c < 24; c++) {
        CP_WAIT0();
        __syncthreads();
        if (c < 23) load_chunk(c + 1, (c + 1) & 1);

        const float* As = Abuf + (c & 1) * SMAT_BUF;
        const float* Bs = Bbuf + (c & 1) * SMAT_BUF;
#pragma unroll
        for (int ks = 0; ks < 4; ks++) {
            unsigned a[4][4], b[4][2];
#pragma unroll
            for (int i = 0; i < 4; i++)
                ldsm4(a[i], As + (wm * 64 + i * 16 + (lane & 15)) * 36
                              + ks * 8 + ((lane >> 4) & 1) * 4);
#pragma unroll
            for (int jp = 0; jp < 2; jp++) {
                unsigned t[4];
                ldsm4(t, Bs + (wn * 32 + jp * 16 + (lane & 7) + ((lane >> 4) & 1) * 8) * 36
                           + ks * 8 + ((lane >> 3) & 1) * 4);
                b[jp * 2][0] = t[0]; b[jp * 2][1] = t[1];
                b[jp * 2 + 1][0] = t[2]; b[jp * 2 + 1][1] = t[3];
            }
#pragma unroll
            for (int i = 0; i < 4; i++)
#pragma unroll
                for (int j = 0; j < 4; j++)
                    mma_tf32(dot[i * 4 + j], a[i], b[j]);
        }

        if ((c & 7) == 7) {                 // view boundary: merge + reset
            int v = c >> 3;
#pragma unroll
            for (int i = 0; i < 4; i++)
#pragma unroll
                for (int j = 0; j < 4; j++) {
                    int t = i * 4 + j;
#pragma unroll
                    for (int e = 0; e < 4; e++) {
                        int rl = wm * 64 + i * 16 + g + ((e >> 1) << 3);
                        int cl = wn * 32 + j * 8 + 2 * tg + (e & 1);
                        if (rm_s[v][rl] && cm_s[v][cl])
                            smax[t][e] = fmaxf(smax[t][e], __expf(dot[t][e] * 5.0f));
                        dot[t][e] = 0.f;
                    }
                }
        }
    }

#pragma unroll
    for (int i = 0; i < 4; i++)
#pragma unroll
        for (int j = 0; j < 4; j++) {
            int t = i * 4 + j;
#pragma unroll
            for (int h = 0; h < 2; h++) {
                int n   = rb * 128 + wm * 64 + i * 16 + g + h * 8;
                int col = cb * 128 + wn * 32 + j * 8 + 2 * tg;
                float v0 = f2tf_f(smax[t][h * 2 + 0]);
                float v1 = f2tf_f(smax[t][h * 2 + 1]);
                if (n == col)     v0 = 0.f;
                if (n == col + 1) v1 = 0.f;
                *(float2*)(g_s + (size_t)n * NN + col) = make_float2(v0, v1);
            }
        }
}

// ---------------- K3: rowsum + confi (masked max, single log) ---------------
__global__ void k_rowstats(const int* __restrict__ mask, float* __restrict__ confi_out) {
    int n = blockIdx.x;
    int tid = threadIdx.x;
    const float4* srow = (const float4*)(g_s + (size_t)n * NN);
    float sum = 0.f, x0 = 0.f, x1 = 0.f, x2 = 0.f;
    for (int m4 = tid; m4 < NN / 4; m4 += 256) {
        float4 sv = srow[m4];
        float lv[4] = {sv.x, sv.y, sv.z, sv.w};
        const int* mp = mask + (size_t)m4 * 4 * NV;
#pragma unroll
        for (int k = 0; k < 4; k++) {
            sum += lv[k];
            if (mp[k * NV + 0]) x0 = fmaxf(x0, lv[k]);
            if (mp[k * NV + 1]) x1 = fmaxf(x1, lv[k]);
            if (mp[k * NV + 2]) x2 = fmaxf(x2, lv[k]);
        }
    }
    __shared__ float rs0[256], rs1[256], rs2[256], rs3[256];
    rs0[tid] = sum; rs1[tid] = x0; rs2[tid] = x1; rs3[tid] = x2;
    __syncthreads();
    for (int off = 128; off > 0; off >>= 1) {
        if (tid < off) {
            rs0[tid] += rs0[tid + off];
            rs1[tid] = fmaxf(rs1[tid], rs1[tid + off]);
            rs2[tid] = fmaxf(rs2[tid], rs2[tid + off]);
            rs3[tid] = fmaxf(rs3[tid], rs3[tid + off]);
        }
        __syncthreads();
    }
    if (tid == 0) {
        g_rowsum[n] = rs0[0];
        // max over masked of 0.2*log(s+1e-9) == 0.2*log(max masked s + 1e-9);
        // unmasked contribute 0 -> fold via clip to [0,1]
        confi_out[0 * NN + n] = fminf(fmaxf(0.2f * __logf(rs1[0] + 1e-9f), 0.f), 1.f);
        confi_out[1 * NN + n] = fminf(fmaxf(0.2f * __logf(rs2[0] + 1e-9f), 0.f), 1.f);
        confi_out[2 * NN + n] = fminf(fmaxf(0.2f * __logf(rs3[0] + 1e-9f), 0.f), 1.f);
    }
}

// ---------------- K4: new_x = (s/rowsum) @ xb_v -> blend -> Z ---------------
// Block 64 rows x 256 h (full H), 8 warps 1x8, warp 64x32. A via ldmatrix.
#define NX_ABUF (64 * 36)
#define NX_BBUF (32 * 264)
__global__ __launch_bounds__(256, 1) void k_newx_tc(const int* __restrict__ mask,
                                                    float* __restrict__ out) {
    int rb = blockIdx.x, v = blockIdx.y;
    int tid = threadIdx.x, lane = tid & 31, wn = tid >> 5;
    int g = lane >> 2, tg = lane & 3;

    extern __shared__ float dyn[];
    float* Abuf = dyn;                       // [2][64*36]
    float* Bbuf = dyn + 2 * NX_ABUF;         // [2][32*264]
    __shared__ float yns[CC * HH];

    for (int l = tid; l < CC * HH; l += 256) yns[l] = g_yn[l];

    const float* xb = g_xb + (size_t)v * NN * HH;

    auto load_chunk = [&](int c, int buf) {
        int m0 = c * 32;
        float* Ab = Abuf + buf * NX_ABUF;
        float* Bb = Bbuf + buf * NX_BBUF;
#pragma unroll
        for (int q = 0; q < 2; q++) {
            int l = q * 256 + tid;
            int r = l >> 3, kq = l & 7;
            cp16(Ab + r * 36 + kq * 4, g_s + (size_t)(rb * 64 + r) * NN + m0 + kq * 4);
        }
#pragma unroll
        for (int q = 0; q < 8; q++) {
            int l = q * 256 + tid;
            int kr = l >> 6, c4 = l & 63;
            cp16(Bb + kr * 264 + c4 * 4, xb + (size_t)(m0 + kr) * HH + c4 * 4);
        }
        CP_COMMIT();
    };

    float acc[16][4];
#pragma unroll
    for (int t = 0; t < 16; t++)
#pragma unroll
        for (int e = 0; e < 4; e++) acc[t][e] = 0.f;

    load_chunk(0, 0);

    for (int c = 0; c < NN / 32; c++) {
        CP_WAIT0();
        __syncthreads();
        if (c < NN / 32 - 1) load_chunk(c + 1, (c + 1) & 1);

        const float* As = Abuf + (c & 1) * NX_ABUF;
        const unsigned* Bs = (const unsigned*)(Bbuf + (c & 1) * NX_BBUF);
#pragma unroll
        for (int ks = 0; ks < 4; ks++) {
            unsigned a[4][4], b[4][2];
#pragma unroll
            for (int i = 0; i < 4; i++)
                ldsm4(a[i], As + (i * 16 + (lane & 15)) * 36
                              + ks * 8 + ((lane >> 4) & 1) * 4);
#pragma unroll
            for (int j = 0; j < 4; j++) {
                int cc = wn * 32 + j * 8 + g;
                b[j][0] = Bs[(ks * 8 + tg) * 264 + cc];
                b[j][1] = Bs[(ks * 8 + tg + 4) * 264 + cc];
            }
#pragma unroll
            for (int i = 0; i < 4; i++)
#pragma unroll
                for (int j = 0; j < 4; j++)
                    mma_tf32(acc[i * 4 + j], a[i], b[j]);
        }
    }

    // epilogue: rowsum scale, mask blend, y_n expansion to Z
#pragma unroll
    for (int i = 0; i < 4; i++)
#pragma unroll
        for (int hh = 0; hh < 2; hh++) {
            int n = rb * 64 + i * 16 + g + hh * 8;
            float rinv = 1.f / (g_rowsum[n] + 1e-9f);
            int mrow = mask[n * NV + v];
            float nx[8];
            if (mrow) {
                const float* xpr = g_xp + ((size_t)v * NN + n) * HH;
#pragma unroll
                for (int j = 0; j < 4; j++) {
                    float2 p = *(const float2*)(xpr + wn * 32 + j * 8 + 2 * tg);
                    nx[j * 2] = p.x; nx[j * 2 + 1] = p.y;
                }
            } else {
#pragma unroll
                for (int j = 0; j < 4; j++) {
                    nx[j * 2]     = acc[i * 4 + j][hh * 2]     * rinv;
                    nx[j * 2 + 1] = acc[i * 4 + j][hh * 2 + 1] * rinv;
                }
            }
            size_t zbase = ((size_t)v * NN + n) * (CC * HH);
#pragma unroll
            for (int c = 0; c < CC; c++) {
#pragma unroll
                for (int j = 0; j < 4; j++) {
                    int col = wn * 32 + j * 8 + 2 * tg;
                    float2 yv = *(const float2*)&yns[c * HH + col];
                    *(float2*)(out + zbase + (size_t)c * HH + col) =
                        make_float2(nx[j * 2] * yv.x, nx[j * 2 + 1] * yv.y);
                }
            }
        }
}

// ---------------- launch ----------------------------------------------------
extern "C" void kernel_launch(void* const* d_in, const int* in_sizes, int n_in,
                              void* d_out, int out_size) {
    ProjPtrs P{};
    RoundPtrs R{};
    const float* yv  = nullptr;
    const float* Wy  = nullptr;
    const float* byp = nullptr;
    const int*   mask = nullptr;
    int nx = 0, nW = 0, nb = 0;
    for (int i = 0; i < n_in; i++) {
        int s = in_sizes[i];
        if      (s == NN * DD)  { if (nx < NV) R.x[nx++] = (const float*)d_in[i]; }
        else if (s == HH * DD)  { if (nW < NV) R.W[nW++] = (const float*)d_in[i]; }
        else if (s == CC * DYY) yv = (const float*)d_in[i];
        else if (s == HH * DYY) Wy = (const float*)d_in[i];
        else if (s == NN * NV)  mask = (const int*)d_in[i];
        else if (s == HH) {
            if (nb < NV) P.b[nb++] = (const float*)d_in[i];
            else         byp = (const float*)d_in[i];
        }
    }
    P.mask = mask;
    float* out = (float*)d_out;
    float* confi_out = out + ((size_t)out_size - (size_t)NV * NN);

    const int proj_dyn = 2 * (PROJ_ABUF + PROJ_BBUF) * (int)sizeof(float);  // 92160
    const int smat_dyn = 4 * SMAT_BUF * (int)sizeof(float);                 // 73728
    const int newx_dyn = 2 * (NX_ABUF + NX_BBUF) * (int)sizeof(float);      // 86016
    cudaFuncSetAttribute(k_proj_tc, cudaFuncAttributeMaxDynamicSharedMemorySize, proj_dyn);
    cudaFuncSetAttribute(k_smat_tc, cudaFuncAttributeMaxDynamicSharedMemorySize, smat_dyn);
    cudaFuncSetAttribute(k_newx_tc, cudaFuncAttributeMaxDynamicSharedMemorySize, newx_dyn);

    int round_total = 3 * (NN * DD / 4) + 3 * (HH * DD / 4);
    k_round   <<<(round_total + 255) / 256, 256>>>(R);
    k_yn      <<<CC, HH>>>(yv, Wy, byp);
    k_proj_tc <<<dim3(NN / 64, NV), 256, proj_dyn>>>(P);
    k_smat_tc <<<dim3(NN / 128, NN / 128), 256, smat_dyn>>>(mask);
    k_rowstats<<<NN, 256>>>(mask, confi_out);
    k_newx_tc <<<dim3(NN / 64, NV), 256, newx_dyn>>>(mask, out);
}